// round 12
// baseline (speedup 1.0000x reference)
#include <cuda_runtime.h>
#include <cuda_bf16.h>
#include <math.h>
#include <stdint.h>

// ---------------- problem constants ----------------
#define C_DIM   1024
#define T_SEQ   2048
#define BATCH   8
#define M_TOTAL (BATCH * T_SEQ)       // 16384

// ---------------- tile config ----------------
#define BM 128
#define BN 128
#define BKF 32                         // k-values per chunk
#define ROWB 64                        // 32 bf16 per row, XOR-swizzled chunks
#define TILEB (128 * ROWB)             // 8192 B per plane tile
#define STAGEB (4 * TILEB)             // Ah,Al,Bh,Bl = 32768 B per stage
#define NSTAGE 3
#define SMEMB  (NSTAGE * STAGEB)       // 98304 B

// ---------------- scratch: split bf16 planes ----------------
__device__ __nv_bfloat16 g_xh [(size_t)M_TOTAL * C_DIM];
__device__ __nv_bfloat16 g_xl [(size_t)M_TOTAL * C_DIM];
__device__ __nv_bfloat16 g_hh [(size_t)3 * M_TOTAL * C_DIM];
__device__ __nv_bfloat16 g_hl [(size_t)3 * M_TOTAL * C_DIM];
__device__ __nv_bfloat16 g_qh [(size_t)3 * M_TOTAL * C_DIM];   // q|k|v planes
__device__ __nv_bfloat16 g_ql [(size_t)3 * M_TOTAL * C_DIM];
__device__ __nv_bfloat16 g_sh [(size_t)BATCH * T_SEQ * T_SEQ];
__device__ __nv_bfloat16 g_sl [(size_t)BATCH * T_SEQ * T_SEQ];
__device__ __nv_bfloat16 g_vth[(size_t)BATCH * C_DIM * T_SEQ];
__device__ __nv_bfloat16 g_vtl[(size_t)BATCH * C_DIM * T_SEQ];
__device__ __nv_bfloat16 g_wh [(size_t)6 * C_DIM * C_DIM];
__device__ __nv_bfloat16 g_wl [(size_t)6 * C_DIM * C_DIM];
__device__ float         g_o  [(size_t)M_TOTAL * C_DIM];

// weight pointer pack for the fused wsplit launch
struct WPack { const float* w[6]; };

// ---------------- helpers ----------------
__device__ __forceinline__ uint32_t smem_u32(const void* p) {
    uint32_t a;
    asm("{ .reg .u64 t; cvta.to.shared.u64 t, %1; cvt.u32.u64 %0, t; }" : "=r"(a) : "l"(p));
    return a;
}
__device__ __forceinline__ void ldsm4(uint32_t* r, uint32_t addr) {
    asm volatile("ldmatrix.sync.aligned.m8n8.x4.shared.b16 {%0,%1,%2,%3}, [%4];"
                 : "=r"(r[0]), "=r"(r[1]), "=r"(r[2]), "=r"(r[3]) : "r"(addr));
}
__device__ __forceinline__ void mma16816(float* c, const uint32_t* a, uint32_t b0, uint32_t b1) {
    asm volatile("mma.sync.aligned.m16n8k16.row.col.f32.bf16.bf16.f32 "
                 "{%0,%1,%2,%3}, {%4,%5,%6,%7}, {%8,%9}, {%0,%1,%2,%3};"
                 : "+f"(c[0]), "+f"(c[1]), "+f"(c[2]), "+f"(c[3])
                 : "r"(a[0]), "r"(a[1]), "r"(a[2]), "r"(a[3]), "r"(b0), "r"(b1));
}
__device__ __forceinline__ void cpa16(uint32_t dst, const void* src) {
    asm volatile("cp.async.cg.shared.global [%0], [%1], 16;" :: "r"(dst), "l"(src));
}
__device__ __forceinline__ void cpa_commit() { asm volatile("cp.async.commit_group;" ::: "memory"); }
template <int N> __device__ __forceinline__ void cpa_wait() {
    asm volatile("cp.async.wait_group %0;" :: "n"(N) : "memory");
}
__device__ __forceinline__ float gelu_exact(float x) {
    return 0.5f * x * (1.0f + erff(x * 0.70710678118654752440f));
}
// (a,b) fp32 -> packed bf16x2 hi + lo
__device__ __forceinline__ void split2(float a, float b, uint32_t& hi, uint32_t& lo) {
    __nv_bfloat162 h = __floats2bfloat162_rn(a, b);
    __nv_bfloat162 l = __floats2bfloat162_rn(a - __bfloat162float(h.x),
                                             b - __bfloat162float(h.y));
    hi = *reinterpret_cast<uint32_t*>(&h);
    lo = *reinterpret_cast<uint32_t*>(&l);
}

// =====================================================================
// bf16x3 tensor-core GEMM on pre-split planes, 3-stage cp.async ring,
// parity-staggered k start. Rolled mainloop (small I-footprint) with
// incremental cycled stage offsets (no %/div in the hot path).
//   C[m,n] = epi( sum_k A[m,k]*B[n,k] ),  A=Ah+Al, B=Bh+Bl
//   EPI: 0 bias+GELU, 1 bias, 2 causal mask*scale, 3 plain
//   TRI:  compact triangular launch (blockIdx.x = linear lower-tri id)
//   CK:   K limit = bm+128 (att causal)
//   REVY: reverse blockIdx.y (longest causal CTAs launch first)
//   OSPLIT: write split bf16 hi/lo planes instead of fp32
// =====================================================================
template <int EPI, bool TRI, bool CK, bool REVY, bool OSPLIT>
__global__ __launch_bounds__(256, 2)
void mma_gemm(const __nv_bfloat16* __restrict__ Ah, const __nv_bfloat16* __restrict__ Al,
              const __nv_bfloat16* __restrict__ Bh, const __nv_bfloat16* __restrict__ Bl,
              const float* __restrict__ b0, const float* __restrict__ b1,
              const float* __restrict__ b2,
              float* __restrict__ Co, __nv_bfloat16* __restrict__ Ch,
              __nv_bfloat16* __restrict__ Cl,
              int lda, int ldb, int ldc, int kdim,
              long long sA, long long sB, long long sC, float scale)
{
    int bm, bn;
    if (TRI) {
        // blockIdx.x = L in [0, 136): lower-triangular (i,j), j <= i
        const int L = (int)blockIdx.x;
        int i = (int)((__fsqrt_rn(8.0f * (float)L + 1.0f) - 1.0f) * 0.5f);
        while ((i + 1) * (i + 2) / 2 <= L) i++;
        while (i * (i + 1) / 2 > L) i--;
        const int j = L - i * (i + 1) / 2;
        bm = i * BM;
        bn = j * BN;
    } else {
        const int by = REVY ? (gridDim.y - 1 - blockIdx.y) : blockIdx.y;
        bm = by * BM;
        bn = blockIdx.x * BN;
    }
    const int z = blockIdx.z;
    Ah += (size_t)z * sA; Al += (size_t)z * sA;
    Bh += (size_t)z * sB; Bl += (size_t)z * sB;
    if (OSPLIT) { Ch += (size_t)z * sC; Cl += (size_t)z * sC; }
    else        { Co += (size_t)z * sC; }
    const float* bias = (z == 0) ? b0 : ((z == 1) ? b1 : b2);

    extern __shared__ __align__(128) char smem[];
    const uint32_t sb = smem_u32(smem);
    const int tid = threadIdx.x, lane = tid & 31, wid = tid >> 5;
    const int wm = (wid >> 1) * 32;
    const int wn = (wid & 1) * 64;

    const int kend = CK ? (bm + BM) : kdim;
    const int NC = kend / BKF;

    // parity-staggered start chunk (breaks some co-resident phase-lock)
    const int par = (int)((blockIdx.x + gridDim.x * (blockIdx.y + gridDim.y * blockIdx.z)) & 1);

    // cp.async mapping: r0 = row, chunk = tid&3, XOR-swizzled by (row>>1)&3
    const int r0 = tid >> 2;
    const int ck = tid & 3;
    const uint32_t sw0 = (uint32_t)((r0 >> 1) & 3);
    const uint32_t so0 = (uint32_t)r0 * ROWB + ((ck ^ sw0) * 16);
    const uint32_t so1 = so0 + 64u * ROWB;
    const int kc = ck * 8;

    // per-thread row base pointers (hoisted once)
    const __nv_bfloat16* pAh0 = Ah + (size_t)(bm + r0) * lda + kc;
    const __nv_bfloat16* pAl0 = Al + (size_t)(bm + r0) * lda + kc;
    const __nv_bfloat16* pBh0 = Bh + (size_t)(bn + r0) * ldb + kc;
    const __nv_bfloat16* pBl0 = Bl + (size_t)(bn + r0) * ldb + kc;
    const __nv_bfloat16* pAh1 = pAh0 + (size_t)64 * lda;
    const __nv_bfloat16* pAl1 = pAl0 + (size_t)64 * lda;
    const __nv_bfloat16* pBh1 = pBh0 + (size_t)64 * ldb;
    const __nv_bfloat16* pBl1 = pBl0 + (size_t)64 * ldb;

    int pn = par * (NC / 2);            // next chunk id to issue (incremental)
    auto issue = [&](uint32_t stgoff) {
        const int k0 = pn * BKF;
        const uint32_t stg = sb + stgoff;
        cpa16(stg + 0 * TILEB + so0, pAh0 + k0);
        cpa16(stg + 1 * TILEB + so0, pAl0 + k0);
        cpa16(stg + 2 * TILEB + so0, pBh0 + k0);
        cpa16(stg + 3 * TILEB + so0, pBl0 + k0);
        cpa16(stg + 0 * TILEB + so1, pAh1 + k0);
        cpa16(stg + 1 * TILEB + so1, pAl1 + k0);
        cpa16(stg + 2 * TILEB + so1, pBh1 + k0);
        cpa16(stg + 3 * TILEB + so1, pBl1 + k0);
        cpa_commit();
        if (++pn == NC) pn = 0;
    };

    float acc[2][8][4];
    #pragma unroll
    for (int mt = 0; mt < 2; mt++)
        #pragma unroll
        for (int nt = 0; nt < 8; nt++)
            #pragma unroll
            for (int e = 0; e < 4; e++) acc[mt][nt][e] = 0.0f;

    const uint32_t lrow = lane & 15;
    const uint32_t lc16 = (uint32_t)(lane >> 4);

    // per-thread ldmatrix row offsets (swizzle folded; chunk XORed at use)
    uint32_t aoff[2], boff[4];
    #pragma unroll
    for (int mt = 0; mt < 2; mt++) {
        const uint32_t row = (uint32_t)(wm + mt * 16) + lrow;
        aoff[mt] = row * ROWB + (((row >> 1) & 3) << 4);
    }
    #pragma unroll
    for (int ng = 0; ng < 4; ng++) {
        const uint32_t row = (uint32_t)(wn + ng * 16) + lrow;
        boff[ng] = row * ROWB + (((row >> 1) & 3) << 4);
    }

    issue(0);
    if (NC > 1) issue(STAGEB);

    uint32_t stoff = 0;                  // stage offset consumed this iter
    uint32_t isoff = 2 * STAGEB;         // stage offset of issue target
    for (int t = 0; t < NC; t++) {
        if (t + 1 < NC) cpa_wait<1>(); else cpa_wait<0>();
        __syncthreads();
        if (t + 2 < NC) issue(isoff);    // targets buffer consumed at t-1
        const uint32_t stg = sb + stoff;
        stoff = (stoff == 2 * STAGEB) ? 0u : stoff + STAGEB;
        isoff = (isoff == 2 * STAGEB) ? 0u : isoff + STAGEB;

        #pragma unroll
        for (int s = 0; s < 2; s++) {
            const uint32_t chunk = ((uint32_t)s * 2 + lc16) << 4;
            uint32_t ah[2][4], al[2][4];
            #pragma unroll
            for (int mt = 0; mt < 2; mt++) {
                const uint32_t ad = stg + (aoff[mt] ^ chunk);
                ldsm4(ah[mt], ad);
                ldsm4(al[mt], ad + 1 * TILEB);
            }
            #pragma unroll
            for (int ng = 0; ng < 4; ng++) {
                uint32_t bh[4], bl[4];
                const uint32_t bd = stg + (boff[ng] ^ chunk);
                ldsm4(bh, bd + 2 * TILEB);
                ldsm4(bl, bd + 3 * TILEB);
                // term 1: Ahi * Bhi (4 independent accumulators)
                mma16816(acc[0][2 * ng],     ah[0], bh[0], bh[2]);
                mma16816(acc[0][2 * ng + 1], ah[0], bh[1], bh[3]);
                mma16816(acc[1][2 * ng],     ah[1], bh[0], bh[2]);
                mma16816(acc[1][2 * ng + 1], ah[1], bh[1], bh[3]);
                // term 2: Ahi * Blo
                mma16816(acc[0][2 * ng],     ah[0], bl[0], bl[2]);
                mma16816(acc[0][2 * ng + 1], ah[0], bl[1], bl[3]);
                mma16816(acc[1][2 * ng],     ah[1], bl[0], bl[2]);
                mma16816(acc[1][2 * ng + 1], ah[1], bl[1], bl[3]);
                // term 3: Alo * Bhi
                mma16816(acc[0][2 * ng],     al[0], bh[0], bh[2]);
                mma16816(acc[0][2 * ng + 1], al[0], bh[1], bh[3]);
                mma16816(acc[1][2 * ng],     al[1], bh[0], bh[2]);
                mma16816(acc[1][2 * ng + 1], al[1], bh[1], bh[3]);
            }
        }
    }

    // ---- epilogue ----
    const int erow = lane >> 2;
    const int ecol = (lane & 3) * 2;
    #pragma unroll
    for (int mt = 0; mt < 2; mt++) {
        #pragma unroll
        for (int nt = 0; nt < 8; nt++) {
            const int gr = bm + wm + mt * 16 + erow;
            const int gc = bn + wn + nt * 8 + ecol;
            float v0 = acc[mt][nt][0], v1 = acc[mt][nt][1];
            float v2 = acc[mt][nt][2], v3 = acc[mt][nt][3];
            if (EPI == 0) {
                const float bb0 = bias[gc], bb1 = bias[gc + 1];
                v0 = gelu_exact(v0 + bb0); v1 = gelu_exact(v1 + bb1);
                v2 = gelu_exact(v2 + bb0); v3 = gelu_exact(v3 + bb1);
            } else if (EPI == 1) {
                const float bb0 = bias[gc], bb1 = bias[gc + 1];
                v0 += bb0; v1 += bb1; v2 += bb0; v3 += bb1;
            } else if (EPI == 2) {
                v0 = (gr     >= gc    ) ? v0 * scale : 0.0f;
                v1 = (gr     >= gc + 1) ? v1 * scale : 0.0f;
                v2 = (gr + 8 >= gc    ) ? v2 * scale : 0.0f;
                v3 = (gr + 8 >= gc + 1) ? v3 * scale : 0.0f;
            }
            if (OSPLIT) {
                uint32_t h01, l01, h23, l23;
                split2(v0, v1, h01, l01);
                split2(v2, v3, h23, l23);
                *reinterpret_cast<uint32_t*>(Ch + (size_t)gr * ldc + gc)       = h01;
                *reinterpret_cast<uint32_t*>(Cl + (size_t)gr * ldc + gc)       = l01;
                *reinterpret_cast<uint32_t*>(Ch + (size_t)(gr + 8) * ldc + gc) = h23;
                *reinterpret_cast<uint32_t*>(Cl + (size_t)(gr + 8) * ldc + gc) = l23;
            } else {
                *reinterpret_cast<float2*>(Co + (size_t)gr * ldc + gc)       = make_float2(v0, v1);
                *reinterpret_cast<float2*>(Co + (size_t)(gr + 8) * ldc + gc) = make_float2(v2, v3);
            }
        }
    }
}

// =====================================================================
// x split: fp32 -> bf16 hi/lo planes
// =====================================================================
__global__ __launch_bounds__(256) void split_x_kernel(
    const float4* __restrict__ x, uint2* __restrict__ hi, uint2* __restrict__ lo)
{
    const int i = blockIdx.x * 256 + threadIdx.x;
    float4 v = x[i];
    uint32_t h01, l01, h23, l23;
    split2(v.x, v.y, h01, l01);
    split2(v.z, v.w, h23, l23);
    hi[i] = make_uint2(h01, h23);
    lo[i] = make_uint2(l01, l23);
}

// =====================================================================
// fused weight transpose+split: all 6 W[k,n] fp32 -> wh/wl [n,k] bf16
// =====================================================================
__global__ __launch_bounds__(256) void wsplit_kernel(
    WPack wp, __nv_bfloat16* __restrict__ wh, __nv_bfloat16* __restrict__ wl)
{
    __shared__ float t[32][33];
    const int z = blockIdx.z;
    const float* W = wp.w[z];
    __nv_bfloat16* whz = wh + (size_t)z * C_DIM * C_DIM;
    __nv_bfloat16* wlz = wl + (size_t)z * C_DIM * C_DIM;
    const int n0 = blockIdx.x * 32, k0 = blockIdx.y * 32;
    const int tx = threadIdx.x, ty = threadIdx.y;
    #pragma unroll
    for (int i = ty; i < 32; i += 8)
        t[i][tx] = W[(size_t)(k0 + i) * C_DIM + n0 + tx];
    __syncthreads();
    #pragma unroll
    for (int i = ty; i < 32; i += 8) {
        float v = t[tx][i];
        __nv_bfloat16 h = __float2bfloat16(v);
        whz[(size_t)(n0 + i) * C_DIM + k0 + tx] = h;
        wlz[(size_t)(n0 + i) * C_DIM + k0 + tx] = __float2bfloat16(v - __bfloat162float(h));
    }
}

// =====================================================================
// V transpose (both planes): [T,C] -> [C,T], batched over z
// =====================================================================
__global__ __launch_bounds__(256) void vtrans_kernel(
    const __nv_bfloat16* __restrict__ vh, const __nv_bfloat16* __restrict__ vl,
    __nv_bfloat16* __restrict__ vth, __nv_bfloat16* __restrict__ vtl)
{
    __shared__ ushort th[32][33], tl[32][33];
    const int z = blockIdx.z;
    const ushort* ph = reinterpret_cast<const ushort*>(vh) + (size_t)z * T_SEQ * C_DIM;
    const ushort* pl = reinterpret_cast<const ushort*>(vl) + (size_t)z * T_SEQ * C_DIM;
    ushort* oh = reinterpret_cast<ushort*>(vth) + (size_t)z * C_DIM * T_SEQ;
    ushort* ol = reinterpret_cast<ushort*>(vtl) + (size_t)z * C_DIM * T_SEQ;
    const int c0 = blockIdx.x * 32, r0 = blockIdx.y * 32;
    const int tx = threadIdx.x, ty = threadIdx.y;
    #pragma unroll
    for (int i = ty; i < 32; i += 8) {
        th[i][tx] = ph[(size_t)(r0 + i) * C_DIM + c0 + tx];
        tl[i][tx] = pl[(size_t)(r0 + i) * C_DIM + c0 + tx];
    }
    __syncthreads();
    #pragma unroll
    for (int i = ty; i < 32; i += 8) {
        oh[(size_t)(c0 + i) * T_SEQ + r0 + tx] = th[tx][i];
        ol[(size_t)(c0 + i) * T_SEQ + r0 + tx] = tl[tx][i];
    }
}

// =====================================================================
// LayerNorm over last dim (C=1024), weight+bias, eps=1e-5
// =====================================================================
__global__ __launch_bounds__(256) void layernorm_kernel(
    const float* __restrict__ X, const float* __restrict__ w,
    const float* __restrict__ bia, float* __restrict__ out)
{
    const int row = blockIdx.x;
    const int tid = threadIdx.x;
    const float* xr = X + (size_t)row * C_DIM;

    float4 v = *reinterpret_cast<const float4*>(&xr[tid * 4]);
    float s  = v.x + v.y + v.z + v.w;
    float sq = v.x * v.x + v.y * v.y + v.z * v.z + v.w * v.w;
    #pragma unroll
    for (int off = 16; off > 0; off >>= 1) {
        s  += __shfl_xor_sync(0xffffffffu, s,  off);
        sq += __shfl_xor_sync(0xffffffffu, sq, off);
    }
    __shared__ float red_s[8], red_q[8];
    const int wid = tid >> 5;
    if ((tid & 31) == 0) { red_s[wid] = s; red_q[wid] = sq; }
    __syncthreads();
    __shared__ float mu_s, inv_s;
    if (tid == 0) {
        float ts = 0.f, tq = 0.f;
        #pragma unroll
        for (int i = 0; i < 8; i++) { ts += red_s[i]; tq += red_q[i]; }
        float mu  = ts * (1.0f / C_DIM);
        float var = tq * (1.0f / C_DIM) - mu * mu;
        mu_s = mu; inv_s = rsqrtf(var + 1e-5f);
    }
    __syncthreads();
    const float mu = mu_s, inv = inv_s;
    float4 wv = *reinterpret_cast<const float4*>(&w[tid * 4]);
    float4 bv = *reinterpret_cast<const float4*>(&bia[tid * 4]);
    float4 o;
    o.x = (v.x - mu) * inv * wv.x + bv.x;
    o.y = (v.y - mu) * inv * wv.y + bv.y;
    o.z = (v.z - mu) * inv * wv.z + bv.z;
    o.w = (v.w - mu) * inv * wv.w + bv.w;
    *reinterpret_cast<float4*>(&out[(size_t)row * C_DIM + tid * 4]) = o;
}

// =====================================================================
// launch
// =====================================================================
extern "C" void kernel_launch(void* const* d_in, const int* in_sizes, int n_in,
                              void* d_out, int out_size)
{
    (void)in_sizes; (void)n_in; (void)out_size;
    const float* x    = (const float*)d_in[0];
    const float* W1q  = (const float*)d_in[1];
    const float* b1q  = (const float*)d_in[2];
    const float* W2q  = (const float*)d_in[3];
    const float* b2q  = (const float*)d_in[4];
    const float* W1k  = (const float*)d_in[5];
    const float* b1k  = (const float*)d_in[6];
    const float* W2k  = (const float*)d_in[7];
    const float* b2k  = (const float*)d_in[8];
    const float* W1v  = (const float*)d_in[9];
    const float* b1v  = (const float*)d_in[10];
    const float* W2v  = (const float*)d_in[11];
    const float* b2v  = (const float*)d_in[12];
    const float* ln_w = (const float*)d_in[13];
    const float* ln_b = (const float*)d_in[14];
    float* out = (float*)d_out;

    __nv_bfloat16 *xh, *xl, *hh, *hl, *qh, *ql, *sh, *sl, *vth, *vtl, *wh, *wl;
    float* o;
    cudaGetSymbolAddress((void**)&xh,  g_xh);  cudaGetSymbolAddress((void**)&xl,  g_xl);
    cudaGetSymbolAddress((void**)&hh,  g_hh);  cudaGetSymbolAddress((void**)&hl,  g_hl);
    cudaGetSymbolAddress((void**)&qh,  g_qh);  cudaGetSymbolAddress((void**)&ql,  g_ql);
    cudaGetSymbolAddress((void**)&sh,  g_sh);  cudaGetSymbolAddress((void**)&sl,  g_sl);
    cudaGetSymbolAddress((void**)&vth, g_vth); cudaGetSymbolAddress((void**)&vtl, g_vtl);
    cudaGetSymbolAddress((void**)&wh,  g_wh);  cudaGetSymbolAddress((void**)&wl,  g_wl);
    cudaGetSymbolAddress((void**)&o,   g_o);

    cudaFuncSetAttribute(mma_gemm<0, false, false, false, true >, cudaFuncAttributeMaxDynamicSharedMemorySize, SMEMB);
    cudaFuncSetAttribute(mma_gemm<1, false, false, false, true >, cudaFuncAttributeMaxDynamicSharedMemorySize, SMEMB);
    cudaFuncSetAttribute(mma_gemm<2, true,  false, false, true >, cudaFuncAttributeMaxDynamicSharedMemorySize, SMEMB);
    cudaFuncSetAttribute(mma_gemm<3, false, true,  true,  false>, cudaFuncAttributeMaxDynamicSharedMemorySize, SMEMB);

    const float inv_scale = 1.0f / sqrtf((float)C_DIM * (float)T_SEQ);
    const long long CC = (long long)C_DIM * C_DIM;
    const long long MC = (long long)M_TOTAL * C_DIM;
    const long long TC = (long long)T_SEQ * C_DIM;
    const long long TT = (long long)T_SEQ * T_SEQ;

    // ---- prep: split x, transpose+split all weights (one launch) ----
    split_x_kernel<<<M_TOTAL * C_DIM / (256 * 4), 256>>>(
        (const float4*)x, (uint2*)xh, (uint2*)xl);
    dim3 tb(32, 8);
    WPack wp; wp.w[0] = W1q; wp.w[1] = W1k; wp.w[2] = W1v;
              wp.w[3] = W2q; wp.w[4] = W2k; wp.w[5] = W2v;
    wsplit_kernel<<<dim3(32, 32, 6), tb>>>(wp, wh, wl);

    // ---- MLP layer 1: h_z = GELU(x @ W1_z + b1_z), split output ----
    mma_gemm<0, false, false, false, true><<<dim3(C_DIM / BN, M_TOTAL / BM, 3), 256, SMEMB>>>(
        xh, xl, wh, wl, b1q, b1k, b1v, nullptr, hh, hl,
        C_DIM, C_DIM, C_DIM, C_DIM, 0, CC, MC, 0.0f);
    // ---- MLP layer 2: qkv_z = h_z @ W2_z + b2_z, split output ----
    mma_gemm<1, false, false, false, true><<<dim3(C_DIM / BN, M_TOTAL / BM, 3), 256, SMEMB>>>(
        hh, hl, wh + 3 * CC, wl + 3 * CC, b2q, b2k, b2v, nullptr, qh, ql,
        C_DIM, C_DIM, C_DIM, C_DIM, MC, CC, MC, 0.0f);

    // ---- V^T per batch (both planes) ----
    vtrans_kernel<<<dim3(C_DIM / 32, T_SEQ / 32, BATCH), tb>>>(
        qh + 2 * MC, ql + 2 * MC, vth, vtl);

    // ---- scores: compact triangular launch (136 lower-tri CTAs/batch) ----
    const int NTRI = (T_SEQ / BM) * (T_SEQ / BM + 1) / 2;   // 136
    mma_gemm<2, true, false, false, true><<<dim3(NTRI, 1, BATCH), 256, SMEMB>>>(
        qh, ql, qh + MC, ql + MC, nullptr, nullptr, nullptr, nullptr, sh, sl,
        C_DIM, C_DIM, T_SEQ, C_DIM, TC, TC, TT, inv_scale);

    // ---- att: O = S @ V (causal K-limit, longest CTAs first), fp32 out ----
    mma_gemm<3, false, true, true, false><<<dim3(C_DIM / BN, T_SEQ / BM, BATCH), 256, SMEMB>>>(
        sh, sl, vth, vtl, nullptr, nullptr, nullptr, o, nullptr, nullptr,
        T_SEQ, T_SEQ, C_DIM, T_SEQ, TT, (long long)C_DIM * T_SEQ, TC, 0.0f);

    layernorm_kernel<<<M_TOTAL, 256>>>(o, ln_w, ln_b, out);
}

// round 13
// speedup vs baseline: 1.0012x; 1.0012x over previous
#include <cuda_runtime.h>
#include <cuda_bf16.h>
#include <math.h>
#include <stdint.h>

// ---------------- problem constants ----------------
#define C_DIM   1024
#define T_SEQ   2048
#define BATCH   8
#define M_TOTAL (BATCH * T_SEQ)       // 16384

// ---------------- tile config ----------------
#define BM 128
#define BN 128
#define BKF 32                         // k-values per chunk
#define ROWB 64                        // 32 bf16 per row, XOR-swizzled chunks
#define TILEB (128 * ROWB)             // 8192 B per plane tile
#define STAGEB (4 * TILEB)             // Ah,Al,Bh,Bl = 32768 B per stage
#define NSTAGE 3
#define SMEMB  (NSTAGE * STAGEB)       // 98304 B

// ---------------- scratch: split bf16 planes ----------------
__device__ __nv_bfloat16 g_xh [(size_t)M_TOTAL * C_DIM];
__device__ __nv_bfloat16 g_xl [(size_t)M_TOTAL * C_DIM];
__device__ __nv_bfloat16 g_hh [(size_t)3 * M_TOTAL * C_DIM];
__device__ __nv_bfloat16 g_hl [(size_t)3 * M_TOTAL * C_DIM];
__device__ __nv_bfloat16 g_qh [(size_t)3 * M_TOTAL * C_DIM];   // q|k|v planes
__device__ __nv_bfloat16 g_ql [(size_t)3 * M_TOTAL * C_DIM];
__device__ __nv_bfloat16 g_sh [(size_t)BATCH * T_SEQ * T_SEQ];
__device__ __nv_bfloat16 g_sl [(size_t)BATCH * T_SEQ * T_SEQ];
__device__ __nv_bfloat16 g_vth[(size_t)BATCH * C_DIM * T_SEQ];
__device__ __nv_bfloat16 g_vtl[(size_t)BATCH * C_DIM * T_SEQ];
__device__ __nv_bfloat16 g_wh [(size_t)6 * C_DIM * C_DIM];
__device__ __nv_bfloat16 g_wl [(size_t)6 * C_DIM * C_DIM];
__device__ float         g_o  [(size_t)M_TOTAL * C_DIM];

// weight pointer pack for the fused wsplit launch
struct WPack { const float* w[6]; };

// ---------------- helpers ----------------
__device__ __forceinline__ uint32_t smem_u32(const void* p) {
    uint32_t a;
    asm("{ .reg .u64 t; cvta.to.shared.u64 t, %1; cvt.u32.u64 %0, t; }" : "=r"(a) : "l"(p));
    return a;
}
__device__ __forceinline__ void ldsm4(uint32_t* r, uint32_t addr) {
    asm volatile("ldmatrix.sync.aligned.m8n8.x4.shared.b16 {%0,%1,%2,%3}, [%4];"
                 : "=r"(r[0]), "=r"(r[1]), "=r"(r[2]), "=r"(r[3]) : "r"(addr));
}
__device__ __forceinline__ void mma16816(float* c, const uint32_t* a, uint32_t b0, uint32_t b1) {
    asm volatile("mma.sync.aligned.m16n8k16.row.col.f32.bf16.bf16.f32 "
                 "{%0,%1,%2,%3}, {%4,%5,%6,%7}, {%8,%9}, {%0,%1,%2,%3};"
                 : "+f"(c[0]), "+f"(c[1]), "+f"(c[2]), "+f"(c[3])
                 : "r"(a[0]), "r"(a[1]), "r"(a[2]), "r"(a[3]), "r"(b0), "r"(b1));
}
__device__ __forceinline__ void cpa16(uint32_t dst, const void* src) {
    asm volatile("cp.async.cg.shared.global [%0], [%1], 16;" :: "r"(dst), "l"(src));
}
__device__ __forceinline__ void cpa_commit() { asm volatile("cp.async.commit_group;" ::: "memory"); }
template <int N> __device__ __forceinline__ void cpa_wait() {
    asm volatile("cp.async.wait_group %0;" :: "n"(N) : "memory");
}
__device__ __forceinline__ float gelu_exact(float x) {
    return 0.5f * x * (1.0f + erff(x * 0.70710678118654752440f));
}
// (a,b) fp32 -> packed bf16x2 hi + lo
__device__ __forceinline__ void split2(float a, float b, uint32_t& hi, uint32_t& lo) {
    __nv_bfloat162 h = __floats2bfloat162_rn(a, b);
    __nv_bfloat162 l = __floats2bfloat162_rn(a - __bfloat162float(h.x),
                                             b - __bfloat162float(h.y));
    hi = *reinterpret_cast<uint32_t*>(&h);
    lo = *reinterpret_cast<uint32_t*>(&l);
}

// =====================================================================
// bf16x3 tensor-core GEMM on pre-split planes, 3-stage cp.async ring,
// parity-staggered k start, rolled mainloop with incremental cycled
// stage offsets (no %/div in the hot path).
//   C[m,n] = epi( sum_k A[m,k]*B[n,k] ),  A=Ah+Al, B=Bh+Bl
//   EPI: 0 bias+GELU, 1 bias, 2 causal mask*scale, 3 plain
//   SKIP: skip CTA if bn > bm+127 (scores upper triangle)
//   CK:   K limit = bm+128 (att causal)
//   REVY: reverse blockIdx.y (longest causal CTAs launch first)
//   OSPLIT: write split bf16 hi/lo planes instead of fp32
// =====================================================================
template <int EPI, bool SKIP, bool CK, bool REVY, bool OSPLIT>
__global__ __launch_bounds__(256, 2)
void mma_gemm(const __nv_bfloat16* __restrict__ Ah, const __nv_bfloat16* __restrict__ Al,
              const __nv_bfloat16* __restrict__ Bh, const __nv_bfloat16* __restrict__ Bl,
              const float* __restrict__ b0, const float* __restrict__ b1,
              const float* __restrict__ b2,
              float* __restrict__ Co, __nv_bfloat16* __restrict__ Ch,
              __nv_bfloat16* __restrict__ Cl,
              int lda, int ldb, int ldc, int kdim,
              long long sA, long long sB, long long sC, float scale)
{
    const int by = REVY ? (gridDim.y - 1 - blockIdx.y) : blockIdx.y;
    const int bm = by * BM;
    const int bn = blockIdx.x * BN;
    if (SKIP && bn > bm + (BM - 1)) return;
    const int z = blockIdx.z;
    Ah += (size_t)z * sA; Al += (size_t)z * sA;
    Bh += (size_t)z * sB; Bl += (size_t)z * sB;
    if (OSPLIT) { Ch += (size_t)z * sC; Cl += (size_t)z * sC; }
    else        { Co += (size_t)z * sC; }
    const float* bias = (z == 0) ? b0 : ((z == 1) ? b1 : b2);

    extern __shared__ __align__(128) char smem[];
    const uint32_t sb = smem_u32(smem);
    const int tid = threadIdx.x, lane = tid & 31, wid = tid >> 5;
    const int wm = (wid >> 1) * 32;
    const int wn = (wid & 1) * 64;

    const int kend = CK ? (bm + BM) : kdim;
    const int NC = kend / BKF;

    // parity-staggered start chunk (breaks some co-resident phase-lock)
    const int par = (int)((blockIdx.x + gridDim.x * (blockIdx.y + gridDim.y * blockIdx.z)) & 1);

    // cp.async mapping: r0 = row, chunk = tid&3, XOR-swizzled by (row>>1)&3
    const int r0 = tid >> 2;
    const int ck = tid & 3;
    const uint32_t sw0 = (uint32_t)((r0 >> 1) & 3);
    const uint32_t so0 = (uint32_t)r0 * ROWB + ((ck ^ sw0) * 16);
    const uint32_t so1 = so0 + 64u * ROWB;
    const int kc = ck * 8;

    // per-thread row base pointers (hoisted once)
    const __nv_bfloat16* pAh0 = Ah + (size_t)(bm + r0) * lda + kc;
    const __nv_bfloat16* pAl0 = Al + (size_t)(bm + r0) * lda + kc;
    const __nv_bfloat16* pBh0 = Bh + (size_t)(bn + r0) * ldb + kc;
    const __nv_bfloat16* pBl0 = Bl + (size_t)(bn + r0) * ldb + kc;
    const __nv_bfloat16* pAh1 = pAh0 + (size_t)64 * lda;
    const __nv_bfloat16* pAl1 = pAl0 + (size_t)64 * lda;
    const __nv_bfloat16* pBh1 = pBh0 + (size_t)64 * ldb;
    const __nv_bfloat16* pBl1 = pBl0 + (size_t)64 * ldb;

    int pn = par * (NC / 2);            // next chunk id to issue (incremental)
    auto issue = [&](uint32_t stgoff) {
        const int k0 = pn * BKF;
        const uint32_t stg = sb + stgoff;
        cpa16(stg + 0 * TILEB + so0, pAh0 + k0);
        cpa16(stg + 1 * TILEB + so0, pAl0 + k0);
        cpa16(stg + 2 * TILEB + so0, pBh0 + k0);
        cpa16(stg + 3 * TILEB + so0, pBl0 + k0);
        cpa16(stg + 0 * TILEB + so1, pAh1 + k0);
        cpa16(stg + 1 * TILEB + so1, pAl1 + k0);
        cpa16(stg + 2 * TILEB + so1, pBh1 + k0);
        cpa16(stg + 3 * TILEB + so1, pBl1 + k0);
        cpa_commit();
        if (++pn == NC) pn = 0;
    };

    float acc[2][8][4];
    #pragma unroll
    for (int mt = 0; mt < 2; mt++)
        #pragma unroll
        for (int nt = 0; nt < 8; nt++)
            #pragma unroll
            for (int e = 0; e < 4; e++) acc[mt][nt][e] = 0.0f;

    const uint32_t lrow = lane & 15;
    const uint32_t lc16 = (uint32_t)(lane >> 4);

    // per-thread ldmatrix row offsets (swizzle folded; chunk XORed at use)
    uint32_t aoff[2], boff[4];
    #pragma unroll
    for (int mt = 0; mt < 2; mt++) {
        const uint32_t row = (uint32_t)(wm + mt * 16) + lrow;
        aoff[mt] = row * ROWB + (((row >> 1) & 3) << 4);
    }
    #pragma unroll
    for (int ng = 0; ng < 4; ng++) {
        const uint32_t row = (uint32_t)(wn + ng * 16) + lrow;
        boff[ng] = row * ROWB + (((row >> 1) & 3) << 4);
    }

    issue(0);
    if (NC > 1) issue(STAGEB);

    uint32_t stoff = 0;                  // stage offset consumed this iter
    uint32_t isoff = 2 * STAGEB;         // stage offset of issue target
    for (int t = 0; t < NC; t++) {
        if (t + 1 < NC) cpa_wait<1>(); else cpa_wait<0>();
        __syncthreads();
        if (t + 2 < NC) issue(isoff);    // targets buffer consumed at t-1
        const uint32_t stg = sb + stoff;
        stoff = (stoff == 2 * STAGEB) ? 0u : stoff + STAGEB;
        isoff = (isoff == 2 * STAGEB) ? 0u : isoff + STAGEB;

        #pragma unroll
        for (int s = 0; s < 2; s++) {
            const uint32_t chunk = ((uint32_t)s * 2 + lc16) << 4;
            uint32_t ah[2][4], al[2][4];
            #pragma unroll
            for (int mt = 0; mt < 2; mt++) {
                const uint32_t ad = stg + (aoff[mt] ^ chunk);
                ldsm4(ah[mt], ad);
                ldsm4(al[mt], ad + 1 * TILEB);
            }
            #pragma unroll
            for (int ng = 0; ng < 4; ng++) {
                uint32_t bh[4], bl[4];
                const uint32_t bd = stg + (boff[ng] ^ chunk);
                ldsm4(bh, bd + 2 * TILEB);
                ldsm4(bl, bd + 3 * TILEB);
                // term 1: Ahi * Bhi (4 independent accumulators)
                mma16816(acc[0][2 * ng],     ah[0], bh[0], bh[2]);
                mma16816(acc[0][2 * ng + 1], ah[0], bh[1], bh[3]);
                mma16816(acc[1][2 * ng],     ah[1], bh[0], bh[2]);
                mma16816(acc[1][2 * ng + 1], ah[1], bh[1], bh[3]);
                // term 2: Ahi * Blo
                mma16816(acc[0][2 * ng],     ah[0], bl[0], bl[2]);
                mma16816(acc[0][2 * ng + 1], ah[0], bl[1], bl[3]);
                mma16816(acc[1][2 * ng],     ah[1], bl[0], bl[2]);
                mma16816(acc[1][2 * ng + 1], ah[1], bl[1], bl[3]);
                // term 3: Alo * Bhi
                mma16816(acc[0][2 * ng],     al[0], bh[0], bh[2]);
                mma16816(acc[0][2 * ng + 1], al[0], bh[1], bh[3]);
                mma16816(acc[1][2 * ng],     al[1], bh[0], bh[2]);
                mma16816(acc[1][2 * ng + 1], al[1], bh[1], bh[3]);
            }
        }
    }

    // ---- epilogue ----
    const int erow = lane >> 2;
    const int ecol = (lane & 3) * 2;
    #pragma unroll
    for (int mt = 0; mt < 2; mt++) {
        #pragma unroll
        for (int nt = 0; nt < 8; nt++) {
            const int gr = bm + wm + mt * 16 + erow;
            const int gc = bn + wn + nt * 8 + ecol;
            float v0 = acc[mt][nt][0], v1 = acc[mt][nt][1];
            float v2 = acc[mt][nt][2], v3 = acc[mt][nt][3];
            if (EPI == 0) {
                const float bb0 = bias[gc], bb1 = bias[gc + 1];
                v0 = gelu_exact(v0 + bb0); v1 = gelu_exact(v1 + bb1);
                v2 = gelu_exact(v2 + bb0); v3 = gelu_exact(v3 + bb1);
            } else if (EPI == 1) {
                const float bb0 = bias[gc], bb1 = bias[gc + 1];
                v0 += bb0; v1 += bb1; v2 += bb0; v3 += bb1;
            } else if (EPI == 2) {
                v0 = (gr     >= gc    ) ? v0 * scale : 0.0f;
                v1 = (gr     >= gc + 1) ? v1 * scale : 0.0f;
                v2 = (gr + 8 >= gc    ) ? v2 * scale : 0.0f;
                v3 = (gr + 8 >= gc + 1) ? v3 * scale : 0.0f;
            }
            if (OSPLIT) {
                uint32_t h01, l01, h23, l23;
                split2(v0, v1, h01, l01);
                split2(v2, v3, h23, l23);
                *reinterpret_cast<uint32_t*>(Ch + (size_t)gr * ldc + gc)       = h01;
                *reinterpret_cast<uint32_t*>(Cl + (size_t)gr * ldc + gc)       = l01;
                *reinterpret_cast<uint32_t*>(Ch + (size_t)(gr + 8) * ldc + gc) = h23;
                *reinterpret_cast<uint32_t*>(Cl + (size_t)(gr + 8) * ldc + gc) = l23;
            } else {
                *reinterpret_cast<float2*>(Co + (size_t)gr * ldc + gc)       = make_float2(v0, v1);
                *reinterpret_cast<float2*>(Co + (size_t)(gr + 8) * ldc + gc) = make_float2(v2, v3);
            }
        }
    }
}

// =====================================================================
// x split: fp32 -> bf16 hi/lo planes
// =====================================================================
__global__ __launch_bounds__(256) void split_x_kernel(
    const float4* __restrict__ x, uint2* __restrict__ hi, uint2* __restrict__ lo)
{
    const int i = blockIdx.x * 256 + threadIdx.x;
    float4 v = x[i];
    uint32_t h01, l01, h23, l23;
    split2(v.x, v.y, h01, l01);
    split2(v.z, v.w, h23, l23);
    hi[i] = make_uint2(h01, h23);
    lo[i] = make_uint2(l01, l23);
}

// =====================================================================
// fused weight transpose+split: all 6 W[k,n] fp32 -> wh/wl [n,k] bf16
// =====================================================================
__global__ __launch_bounds__(256) void wsplit_kernel(
    WPack wp, __nv_bfloat16* __restrict__ wh, __nv_bfloat16* __restrict__ wl)
{
    __shared__ float t[32][33];
    const int z = blockIdx.z;
    const float* W = wp.w[z];
    __nv_bfloat16* whz = wh + (size_t)z * C_DIM * C_DIM;
    __nv_bfloat16* wlz = wl + (size_t)z * C_DIM * C_DIM;
    const int n0 = blockIdx.x * 32, k0 = blockIdx.y * 32;
    const int tx = threadIdx.x, ty = threadIdx.y;
    #pragma unroll
    for (int i = ty; i < 32; i += 8)
        t[i][tx] = W[(size_t)(k0 + i) * C_DIM + n0 + tx];
    __syncthreads();
    #pragma unroll
    for (int i = ty; i < 32; i += 8) {
        float v = t[tx][i];
        __nv_bfloat16 h = __float2bfloat16(v);
        whz[(size_t)(n0 + i) * C_DIM + k0 + tx] = h;
        wlz[(size_t)(n0 + i) * C_DIM + k0 + tx] = __float2bfloat16(v - __bfloat162float(h));
    }
}

// =====================================================================
// V transpose (both planes): [T,C] -> [C,T], batched over z
// =====================================================================
__global__ __launch_bounds__(256) void vtrans_kernel(
    const __nv_bfloat16* __restrict__ vh, const __nv_bfloat16* __restrict__ vl,
    __nv_bfloat16* __restrict__ vth, __nv_bfloat16* __restrict__ vtl)
{
    __shared__ ushort th[32][33], tl[32][33];
    const int z = blockIdx.z;
    const ushort* ph = reinterpret_cast<const ushort*>(vh) + (size_t)z * T_SEQ * C_DIM;
    const ushort* pl = reinterpret_cast<const ushort*>(vl) + (size_t)z * T_SEQ * C_DIM;
    ushort* oh = reinterpret_cast<ushort*>(vth) + (size_t)z * C_DIM * T_SEQ;
    ushort* ol = reinterpret_cast<ushort*>(vtl) + (size_t)z * C_DIM * T_SEQ;
    const int c0 = blockIdx.x * 32, r0 = blockIdx.y * 32;
    const int tx = threadIdx.x, ty = threadIdx.y;
    #pragma unroll
    for (int i = ty; i < 32; i += 8) {
        th[i][tx] = ph[(size_t)(r0 + i) * C_DIM + c0 + tx];
        tl[i][tx] = pl[(size_t)(r0 + i) * C_DIM + c0 + tx];
    }
    __syncthreads();
    #pragma unroll
    for (int i = ty; i < 32; i += 8) {
        oh[(size_t)(c0 + i) * T_SEQ + r0 + tx] = th[tx][i];
        ol[(size_t)(c0 + i) * T_SEQ + r0 + tx] = tl[tx][i];
    }
}

// =====================================================================
// LayerNorm over last dim (C=1024), weight+bias, eps=1e-5
// =====================================================================
__global__ __launch_bounds__(256) void layernorm_kernel(
    const float* __restrict__ X, const float* __restrict__ w,
    const float* __restrict__ bia, float* __restrict__ out)
{
    const int row = blockIdx.x;
    const int tid = threadIdx.x;
    const float* xr = X + (size_t)row * C_DIM;

    float4 v = *reinterpret_cast<const float4*>(&xr[tid * 4]);
    float s  = v.x + v.y + v.z + v.w;
    float sq = v.x * v.x + v.y * v.y + v.z * v.z + v.w * v.w;
    #pragma unroll
    for (int off = 16; off > 0; off >>= 1) {
        s  += __shfl_xor_sync(0xffffffffu, s,  off);
        sq += __shfl_xor_sync(0xffffffffu, sq, off);
    }
    __shared__ float red_s[8], red_q[8];
    const int wid = tid >> 5;
    if ((tid & 31) == 0) { red_s[wid] = s; red_q[wid] = sq; }
    __syncthreads();
    __shared__ float mu_s, inv_s;
    if (tid == 0) {
        float ts = 0.f, tq = 0.f;
        #pragma unroll
        for (int i = 0; i < 8; i++) { ts += red_s[i]; tq += red_q[i]; }
        float mu  = ts * (1.0f / C_DIM);
        float var = tq * (1.0f / C_DIM) - mu * mu;
        mu_s = mu; inv_s = rsqrtf(var + 1e-5f);
    }
    __syncthreads();
    const float mu = mu_s, inv = inv_s;
    float4 wv = *reinterpret_cast<const float4*>(&w[tid * 4]);
    float4 bv = *reinterpret_cast<const float4*>(&bia[tid * 4]);
    float4 o;
    o.x = (v.x - mu) * inv * wv.x + bv.x;
    o.y = (v.y - mu) * inv * wv.y + bv.y;
    o.z = (v.z - mu) * inv * wv.z + bv.z;
    o.w = (v.w - mu) * inv * wv.w + bv.w;
    *reinterpret_cast<float4*>(&out[(size_t)row * C_DIM + tid * 4]) = o;
}

// =====================================================================
// launch
// =====================================================================
extern "C" void kernel_launch(void* const* d_in, const int* in_sizes, int n_in,
                              void* d_out, int out_size)
{
    (void)in_sizes; (void)n_in; (void)out_size;
    const float* x    = (const float*)d_in[0];
    const float* W1q  = (const float*)d_in[1];
    const float* b1q  = (const float*)d_in[2];
    const float* W2q  = (const float*)d_in[3];
    const float* b2q  = (const float*)d_in[4];
    const float* W1k  = (const float*)d_in[5];
    const float* b1k  = (const float*)d_in[6];
    const float* W2k  = (const float*)d_in[7];
    const float* b2k  = (const float*)d_in[8];
    const float* W1v  = (const float*)d_in[9];
    const float* b1v  = (const float*)d_in[10];
    const float* W2v  = (const float*)d_in[11];
    const float* b2v  = (const float*)d_in[12];
    const float* ln_w = (const float*)d_in[13];
    const float* ln_b = (const float*)d_in[14];
    float* out = (float*)d_out;

    __nv_bfloat16 *xh, *xl, *hh, *hl, *qh, *ql, *sh, *sl, *vth, *vtl, *wh, *wl;
    float* o;
    cudaGetSymbolAddress((void**)&xh,  g_xh);  cudaGetSymbolAddress((void**)&xl,  g_xl);
    cudaGetSymbolAddress((void**)&hh,  g_hh);  cudaGetSymbolAddress((void**)&hl,  g_hl);
    cudaGetSymbolAddress((void**)&qh,  g_qh);  cudaGetSymbolAddress((void**)&ql,  g_ql);
    cudaGetSymbolAddress((void**)&sh,  g_sh);  cudaGetSymbolAddress((void**)&sl,  g_sl);
    cudaGetSymbolAddress((void**)&vth, g_vth); cudaGetSymbolAddress((void**)&vtl, g_vtl);
    cudaGetSymbolAddress((void**)&wh,  g_wh);  cudaGetSymbolAddress((void**)&wl,  g_wl);
    cudaGetSymbolAddress((void**)&o,   g_o);

    cudaFuncSetAttribute(mma_gemm<0, false, false, false, true >, cudaFuncAttributeMaxDynamicSharedMemorySize, SMEMB);
    cudaFuncSetAttribute(mma_gemm<1, false, false, false, true >, cudaFuncAttributeMaxDynamicSharedMemorySize, SMEMB);
    cudaFuncSetAttribute(mma_gemm<2, true,  false, false, true >, cudaFuncAttributeMaxDynamicSharedMemorySize, SMEMB);
    cudaFuncSetAttribute(mma_gemm<3, false, true,  true,  false>, cudaFuncAttributeMaxDynamicSharedMemorySize, SMEMB);

    const float inv_scale = 1.0f / sqrtf((float)C_DIM * (float)T_SEQ);
    const long long CC = (long long)C_DIM * C_DIM;
    const long long MC = (long long)M_TOTAL * C_DIM;
    const long long TC = (long long)T_SEQ * C_DIM;
    const long long TT = (long long)T_SEQ * T_SEQ;

    // ---- prep: split x, transpose+split all weights (one launch) ----
    split_x_kernel<<<M_TOTAL * C_DIM / (256 * 4), 256>>>(
        (const float4*)x, (uint2*)xh, (uint2*)xl);
    dim3 tb(32, 8);
    WPack wp; wp.w[0] = W1q; wp.w[1] = W1k; wp.w[2] = W1v;
              wp.w[3] = W2q; wp.w[4] = W2k; wp.w[5] = W2v;
    wsplit_kernel<<<dim3(32, 32, 6), tb>>>(wp, wh, wl);

    // ---- MLP layer 1: h_z = GELU(x @ W1_z + b1_z), split output ----
    mma_gemm<0, false, false, false, true><<<dim3(C_DIM / BN, M_TOTAL / BM, 3), 256, SMEMB>>>(
        xh, xl, wh, wl, b1q, b1k, b1v, nullptr, hh, hl,
        C_DIM, C_DIM, C_DIM, C_DIM, 0, CC, MC, 0.0f);
    // ---- MLP layer 2: qkv_z = h_z @ W2_z + b2_z, split output ----
    mma_gemm<1, false, false, false, true><<<dim3(C_DIM / BN, M_TOTAL / BM, 3), 256, SMEMB>>>(
        hh, hl, wh + 3 * CC, wl + 3 * CC, b2q, b2k, b2v, nullptr, qh, ql,
        C_DIM, C_DIM, C_DIM, C_DIM, MC, CC, MC, 0.0f);

    // ---- V^T per batch (both planes) ----
    vtrans_kernel<<<dim3(C_DIM / 32, T_SEQ / 32, BATCH), tb>>>(
        qh + 2 * MC, ql + 2 * MC, vth, vtl);

    // ---- scores: S = mask(i>=j) * (q.k) * inv_scale, split output ----
    mma_gemm<2, true, false, false, true><<<dim3(T_SEQ / BN, T_SEQ / BM, BATCH), 256, SMEMB>>>(
        qh, ql, qh + MC, ql + MC, nullptr, nullptr, nullptr, nullptr, sh, sl,
        C_DIM, C_DIM, T_SEQ, C_DIM, TC, TC, TT, inv_scale);

    // ---- att: O = S @ V (causal K-limit, longest CTAs first), fp32 out ----
    mma_gemm<3, false, true, true, false><<<dim3(C_DIM / BN, T_SEQ / BM, BATCH), 256, SMEMB>>>(
        sh, sl, vth, vtl, nullptr, nullptr, nullptr, o, nullptr, nullptr,
        T_SEQ, T_SEQ, C_DIM, T_SEQ, TT, (long long)C_DIM * T_SEQ, TC, 0.0f);

    layernorm_kernel<<<M_TOTAL, 256>>>(o, ln_w, ln_b, out);
}

// round 14
// speedup vs baseline: 1.0086x; 1.0074x over previous
#include <cuda_runtime.h>
#include <cuda_bf16.h>
#include <math.h>
#include <stdint.h>

// ---------------- problem constants ----------------
#define C_DIM   1024
#define T_SEQ   2048
#define BATCH   8
#define M_TOTAL (BATCH * T_SEQ)       // 16384

// ---------------- tile config ----------------
#define BM 128
#define BN 128
#define BKF 32                         // k-values per chunk
#define ROWB 64                        // 32 bf16 per row, XOR-swizzled chunks
#define TILEB (128 * ROWB)             // 8192 B per plane tile
#define STAGEB (4 * TILEB)             // Ah,Al,Bh,Bl = 32768 B per stage
#define NSTAGE 3
#define SMEMB  (NSTAGE * STAGEB)       // 98304 B

// ---------------- scratch: split bf16 planes ----------------
__device__ __nv_bfloat16 g_xh [(size_t)M_TOTAL * C_DIM];
__device__ __nv_bfloat16 g_xl [(size_t)M_TOTAL * C_DIM];
__device__ __nv_bfloat16 g_hh [(size_t)3 * M_TOTAL * C_DIM];
__device__ __nv_bfloat16 g_hl [(size_t)3 * M_TOTAL * C_DIM];
__device__ __nv_bfloat16 g_qh [(size_t)3 * M_TOTAL * C_DIM];   // q|k|v planes
__device__ __nv_bfloat16 g_ql [(size_t)3 * M_TOTAL * C_DIM];
__device__ __nv_bfloat16 g_sh [(size_t)BATCH * T_SEQ * T_SEQ];
__device__ __nv_bfloat16 g_sl [(size_t)BATCH * T_SEQ * T_SEQ];
__device__ __nv_bfloat16 g_vth[(size_t)BATCH * C_DIM * T_SEQ];
__device__ __nv_bfloat16 g_vtl[(size_t)BATCH * C_DIM * T_SEQ];
__device__ __nv_bfloat16 g_wh [(size_t)6 * C_DIM * C_DIM];
__device__ __nv_bfloat16 g_wl [(size_t)6 * C_DIM * C_DIM];
__device__ float         g_o  [(size_t)M_TOTAL * C_DIM];

// weight pointer pack for the fused wsplit launch
struct WPack { const float* w[6]; };

// ---------------- helpers ----------------
__device__ __forceinline__ uint32_t smem_u32(const void* p) {
    uint32_t a;
    asm("{ .reg .u64 t; cvta.to.shared.u64 t, %1; cvt.u32.u64 %0, t; }" : "=r"(a) : "l"(p));
    return a;
}
__device__ __forceinline__ void ldsm4(uint32_t* r, uint32_t addr) {
    asm volatile("ldmatrix.sync.aligned.m8n8.x4.shared.b16 {%0,%1,%2,%3}, [%4];"
                 : "=r"(r[0]), "=r"(r[1]), "=r"(r[2]), "=r"(r[3]) : "r"(addr));
}
__device__ __forceinline__ void mma16816(float* c, const uint32_t* a, uint32_t b0, uint32_t b1) {
    asm volatile("mma.sync.aligned.m16n8k16.row.col.f32.bf16.bf16.f32 "
                 "{%0,%1,%2,%3}, {%4,%5,%6,%7}, {%8,%9}, {%0,%1,%2,%3};"
                 : "+f"(c[0]), "+f"(c[1]), "+f"(c[2]), "+f"(c[3])
                 : "r"(a[0]), "r"(a[1]), "r"(a[2]), "r"(a[3]), "r"(b0), "r"(b1));
}
__device__ __forceinline__ void cpa16(uint32_t dst, const void* src) {
    asm volatile("cp.async.cg.shared.global [%0], [%1], 16;" :: "r"(dst), "l"(src));
}
__device__ __forceinline__ void cpa_commit() { asm volatile("cp.async.commit_group;" ::: "memory"); }
template <int N> __device__ __forceinline__ void cpa_wait() {
    asm volatile("cp.async.wait_group %0;" :: "n"(N) : "memory");
}
__device__ __forceinline__ float gelu_exact(float x) {
    return 0.5f * x * (1.0f + erff(x * 0.70710678118654752440f));
}
// (a,b) fp32 -> packed bf16x2 hi + lo
__device__ __forceinline__ void split2(float a, float b, uint32_t& hi, uint32_t& lo) {
    __nv_bfloat162 h = __floats2bfloat162_rn(a, b);
    __nv_bfloat162 l = __floats2bfloat162_rn(a - __bfloat162float(h.x),
                                             b - __bfloat162float(h.y));
    hi = *reinterpret_cast<uint32_t*>(&h);
    lo = *reinterpret_cast<uint32_t*>(&l);
}

// =====================================================================
// bf16x3 tensor-core GEMM on pre-split planes, 3-stage cp.async ring,
// with parity-staggered k-loop start.
//   C[m,n] = epi( sum_k A[m,k]*B[n,k] ),  A=Ah+Al, B=Bh+Bl
//   EPI: 0 bias+GELU, 1 bias, 2 causal mask*scale, 3 plain
//   SKIP: skip CTA if bn > bm+127; CK: K limit = bm+128
//   REVY: reverse blockIdx.y (longest causal CTAs launch first)
//   OSPLIT: write split bf16 hi/lo planes instead of fp32
// =====================================================================
template <int EPI, bool SKIP, bool CK, bool REVY, bool OSPLIT>
__global__ __launch_bounds__(256, 2)
void mma_gemm(const __nv_bfloat16* __restrict__ Ah, const __nv_bfloat16* __restrict__ Al,
              const __nv_bfloat16* __restrict__ Bh, const __nv_bfloat16* __restrict__ Bl,
              const float* __restrict__ b0, const float* __restrict__ b1,
              const float* __restrict__ b2,
              float* __restrict__ Co, __nv_bfloat16* __restrict__ Ch,
              __nv_bfloat16* __restrict__ Cl,
              int lda, int ldb, int ldc, int kdim,
              long long sA, long long sB, long long sC, float scale)
{
    const int by = REVY ? (gridDim.y - 1 - blockIdx.y) : blockIdx.y;
    const int bm = by * BM;
    const int bn = blockIdx.x * BN;
    if (SKIP && bn > bm + (BM - 1)) return;
    const int z = blockIdx.z;
    Ah += (size_t)z * sA; Al += (size_t)z * sA;
    Bh += (size_t)z * sB; Bl += (size_t)z * sB;
    if (OSPLIT) { Ch += (size_t)z * sC; Cl += (size_t)z * sC; }
    else        { Co += (size_t)z * sC; }
    const float* bias = (z == 0) ? b0 : ((z == 1) ? b1 : b2);

    extern __shared__ __align__(128) char smem[];
    const uint32_t sb = smem_u32(smem);
    const int tid = threadIdx.x, lane = tid & 31, wid = tid >> 5;
    const int wm = (wid >> 1) * 32;
    const int wn = (wid & 1) * 64;

    const int kend = CK ? (bm + BM) : kdim;
    const int NC = kend / BKF;

    // parity of linear bid approximates co-residency pairing; odd CTAs
    // start half a k-loop ahead -> barriers interleave across the pair
    const int par = (int)((blockIdx.x + gridDim.x * (blockIdx.y + gridDim.y * blockIdx.z)) & 1);
    const int c0 = par * (NC / 2);

    // cp.async mapping: r0 = row, chunk c = tid&3, XOR-swizzled by (row>>1)&3
    const int r0 = tid >> 2;
    const int ck = tid & 3;
    const uint32_t sw0 = (uint32_t)((r0 >> 1) & 3);             // same for r0 and r0+64
    const uint32_t so0 = (uint32_t)r0 * ROWB + ((ck ^ sw0) * 16);
    const uint32_t so1 = so0 + 64u * ROWB;
    const int kc = ck * 8;                                       // bf16 elem offset

    auto issue = [&](int t) {
        int p = c0 + t; if (p >= NC) p -= NC;                    // staggered chunk id
        const int k0 = p * BKF;
        const uint32_t stg = sb + (uint32_t)(t % NSTAGE) * STAGEB;
        cpa16(stg + 0 * TILEB + so0, Ah + (size_t)(bm + r0) * lda + k0 + kc);
        cpa16(stg + 1 * TILEB + so0, Al + (size_t)(bm + r0) * lda + k0 + kc);
        cpa16(stg + 2 * TILEB + so0, Bh + (size_t)(bn + r0) * ldb + k0 + kc);
        cpa16(stg + 3 * TILEB + so0, Bl + (size_t)(bn + r0) * ldb + k0 + kc);
        cpa16(stg + 0 * TILEB + so1, Ah + (size_t)(bm + r0 + 64) * lda + k0 + kc);
        cpa16(stg + 1 * TILEB + so1, Al + (size_t)(bm + r0 + 64) * lda + k0 + kc);
        cpa16(stg + 2 * TILEB + so1, Bh + (size_t)(bn + r0 + 64) * ldb + k0 + kc);
        cpa16(stg + 3 * TILEB + so1, Bl + (size_t)(bn + r0 + 64) * ldb + k0 + kc);
        cpa_commit();
    };

    float acc[2][8][4];
    #pragma unroll
    for (int mt = 0; mt < 2; mt++)
        #pragma unroll
        for (int nt = 0; nt < 8; nt++)
            #pragma unroll
            for (int e = 0; e < 4; e++) acc[mt][nt][e] = 0.0f;

    const uint32_t lrow = lane & 15;
    const uint32_t lc16 = (uint32_t)(lane >> 4);   // chunk sub-index from lane

    // precompute per-thread ldmatrix row offsets (swizzle depends on row)
    uint32_t aoff[2], boff[4];
    #pragma unroll
    for (int mt = 0; mt < 2; mt++) {
        const uint32_t row = (uint32_t)(wm + mt * 16) + lrow;
        aoff[mt] = row * ROWB + (((row >> 1) & 3) << 4);
    }
    #pragma unroll
    for (int ng = 0; ng < 4; ng++) {
        const uint32_t row = (uint32_t)(wn + ng * 16) + lrow;
        boff[ng] = row * ROWB + (((row >> 1) & 3) << 4);
    }

    issue(0);
    if (NC > 1) issue(1);

    for (int t = 0; t < NC; t++) {
        if (t + 1 < NC) cpa_wait<1>(); else cpa_wait<0>();
        __syncthreads();
        if (t + 2 < NC) issue(t + 2);    // safe: targets buffer consumed at t-1
        const uint32_t stg = sb + (uint32_t)(t % NSTAGE) * STAGEB;

        #pragma unroll
        for (int s = 0; s < 2; s++) {
            const uint32_t chunk = ((uint32_t)s * 2 + lc16) << 4;
            uint32_t ah[2][4], al[2][4];
            #pragma unroll
            for (int mt = 0; mt < 2; mt++) {
                const uint32_t ad = stg + (aoff[mt] ^ chunk);
                ldsm4(ah[mt], ad);
                ldsm4(al[mt], ad + 1 * TILEB);
            }
            #pragma unroll
            for (int ng = 0; ng < 4; ng++) {
                uint32_t bh[4], bl[4];
                const uint32_t bd = stg + (boff[ng] ^ chunk);
                ldsm4(bh, bd + 2 * TILEB);
                ldsm4(bl, bd + 3 * TILEB);
                // term 1: Ahi * Bhi  (4 independent accumulators)
                mma16816(acc[0][2 * ng],     ah[0], bh[0], bh[2]);
                mma16816(acc[0][2 * ng + 1], ah[0], bh[1], bh[3]);
                mma16816(acc[1][2 * ng],     ah[1], bh[0], bh[2]);
                mma16816(acc[1][2 * ng + 1], ah[1], bh[1], bh[3]);
                // term 2: Ahi * Blo
                mma16816(acc[0][2 * ng],     ah[0], bl[0], bl[2]);
                mma16816(acc[0][2 * ng + 1], ah[0], bl[1], bl[3]);
                mma16816(acc[1][2 * ng],     ah[1], bl[0], bl[2]);
                mma16816(acc[1][2 * ng + 1], ah[1], bl[1], bl[3]);
                // term 3: Alo * Bhi
                mma16816(acc[0][2 * ng],     al[0], bh[0], bh[2]);
                mma16816(acc[0][2 * ng + 1], al[0], bh[1], bh[3]);
                mma16816(acc[1][2 * ng],     al[1], bh[0], bh[2]);
                mma16816(acc[1][2 * ng + 1], al[1], bh[1], bh[3]);
            }
        }
    }

    // ---- epilogue ----
    const int erow = lane >> 2;
    const int ecol = (lane & 3) * 2;
    #pragma unroll
    for (int mt = 0; mt < 2; mt++) {
        #pragma unroll
        for (int nt = 0; nt < 8; nt++) {
            const int gr = bm + wm + mt * 16 + erow;
            const int gc = bn + wn + nt * 8 + ecol;
            float v0 = acc[mt][nt][0], v1 = acc[mt][nt][1];
            float v2 = acc[mt][nt][2], v3 = acc[mt][nt][3];
            if (EPI == 0) {
                const float bb0 = bias[gc], bb1 = bias[gc + 1];
                v0 = gelu_exact(v0 + bb0); v1 = gelu_exact(v1 + bb1);
                v2 = gelu_exact(v2 + bb0); v3 = gelu_exact(v3 + bb1);
            } else if (EPI == 1) {
                const float bb0 = bias[gc], bb1 = bias[gc + 1];
                v0 += bb0; v1 += bb1; v2 += bb0; v3 += bb1;
            } else if (EPI == 2) {
                v0 = (gr     >= gc    ) ? v0 * scale : 0.0f;
                v1 = (gr     >= gc + 1) ? v1 * scale : 0.0f;
                v2 = (gr + 8 >= gc    ) ? v2 * scale : 0.0f;
                v3 = (gr + 8 >= gc + 1) ? v3 * scale : 0.0f;
            }
            if (OSPLIT) {
                uint32_t h01, l01, h23, l23;
                split2(v0, v1, h01, l01);
                split2(v2, v3, h23, l23);
                *reinterpret_cast<uint32_t*>(Ch + (size_t)gr * ldc + gc)       = h01;
                *reinterpret_cast<uint32_t*>(Cl + (size_t)gr * ldc + gc)       = l01;
                *reinterpret_cast<uint32_t*>(Ch + (size_t)(gr + 8) * ldc + gc) = h23;
                *reinterpret_cast<uint32_t*>(Cl + (size_t)(gr + 8) * ldc + gc) = l23;
            } else {
                *reinterpret_cast<float2*>(Co + (size_t)gr * ldc + gc)       = make_float2(v0, v1);
                *reinterpret_cast<float2*>(Co + (size_t)(gr + 8) * ldc + gc) = make_float2(v2, v3);
            }
        }
    }
}

// =====================================================================
// x split: fp32 -> bf16 hi/lo planes
// =====================================================================
__global__ __launch_bounds__(256) void split_x_kernel(
    const float4* __restrict__ x, uint2* __restrict__ hi, uint2* __restrict__ lo)
{
    const int i = blockIdx.x * 256 + threadIdx.x;
    float4 v = x[i];
    uint32_t h01, l01, h23, l23;
    split2(v.x, v.y, h01, l01);
    split2(v.z, v.w, h23, l23);
    hi[i] = make_uint2(h01, h23);
    lo[i] = make_uint2(l01, l23);
}

// =====================================================================
// fused weight transpose+split: all 6 W[k,n] fp32 -> wh/wl [n,k] bf16
// =====================================================================
__global__ __launch_bounds__(256) void wsplit_kernel(
    WPack wp, __nv_bfloat16* __restrict__ wh, __nv_bfloat16* __restrict__ wl)
{
    __shared__ float t[32][33];
    const int z = blockIdx.z;
    const float* W = wp.w[z];
    __nv_bfloat16* whz = wh + (size_t)z * C_DIM * C_DIM;
    __nv_bfloat16* wlz = wl + (size_t)z * C_DIM * C_DIM;
    const int n0 = blockIdx.x * 32, k0 = blockIdx.y * 32;
    const int tx = threadIdx.x, ty = threadIdx.y;
    #pragma unroll
    for (int i = ty; i < 32; i += 8)
        t[i][tx] = W[(size_t)(k0 + i) * C_DIM + n0 + tx];
    __syncthreads();
    #pragma unroll
    for (int i = ty; i < 32; i += 8) {
        float v = t[tx][i];
        __nv_bfloat16 h = __float2bfloat16(v);
        whz[(size_t)(n0 + i) * C_DIM + k0 + tx] = h;
        wlz[(size_t)(n0 + i) * C_DIM + k0 + tx] = __float2bfloat16(v - __bfloat162float(h));
    }
}

// =====================================================================
// V transpose (both planes): [T,C] -> [C,T], batched over z
// =====================================================================
__global__ __launch_bounds__(256) void vtrans_kernel(
    const __nv_bfloat16* __restrict__ vh, const __nv_bfloat16* __restrict__ vl,
    __nv_bfloat16* __restrict__ vth, __nv_bfloat16* __restrict__ vtl)
{
    __shared__ ushort th[32][33], tl[32][33];
    const int z = blockIdx.z;
    const ushort* ph = reinterpret_cast<const ushort*>(vh) + (size_t)z * T_SEQ * C_DIM;
    const ushort* pl = reinterpret_cast<const ushort*>(vl) + (size_t)z * T_SEQ * C_DIM;
    ushort* oh = reinterpret_cast<ushort*>(vth) + (size_t)z * C_DIM * T_SEQ;
    ushort* ol = reinterpret_cast<ushort*>(vtl) + (size_t)z * C_DIM * T_SEQ;
    const int c0 = blockIdx.x * 32, r0 = blockIdx.y * 32;
    const int tx = threadIdx.x, ty = threadIdx.y;
    #pragma unroll
    for (int i = ty; i < 32; i += 8) {
        th[i][tx] = ph[(size_t)(r0 + i) * C_DIM + c0 + tx];
        tl[i][tx] = pl[(size_t)(r0 + i) * C_DIM + c0 + tx];
    }
    __syncthreads();
    #pragma unroll
    for (int i = ty; i < 32; i += 8) {
        oh[(size_t)(c0 + i) * T_SEQ + r0 + tx] = th[tx][i];
        ol[(size_t)(c0 + i) * T_SEQ + r0 + tx] = tl[tx][i];
    }
}

// =====================================================================
// LayerNorm over last dim (C=1024), weight+bias, eps=1e-5
// =====================================================================
__global__ __launch_bounds__(256) void layernorm_kernel(
    const float* __restrict__ X, const float* __restrict__ w,
    const float* __restrict__ bia, float* __restrict__ out)
{
    const int row = blockIdx.x;
    const int tid = threadIdx.x;
    const float* xr = X + (size_t)row * C_DIM;

    float4 v = *reinterpret_cast<const float4*>(&xr[tid * 4]);
    float s  = v.x + v.y + v.z + v.w;
    float sq = v.x * v.x + v.y * v.y + v.z * v.z + v.w * v.w;
    #pragma unroll
    for (int off = 16; off > 0; off >>= 1) {
        s  += __shfl_xor_sync(0xffffffffu, s,  off);
        sq += __shfl_xor_sync(0xffffffffu, sq, off);
    }
    __shared__ float red_s[8], red_q[8];
    const int wid = tid >> 5;
    if ((tid & 31) == 0) { red_s[wid] = s; red_q[wid] = sq; }
    __syncthreads();
    __shared__ float mu_s, inv_s;
    if (tid == 0) {
        float ts = 0.f, tq = 0.f;
        #pragma unroll
        for (int i = 0; i < 8; i++) { ts += red_s[i]; tq += red_q[i]; }
        float mu  = ts * (1.0f / C_DIM);
        float var = tq * (1.0f / C_DIM) - mu * mu;
        mu_s = mu; inv_s = rsqrtf(var + 1e-5f);
    }
    __syncthreads();
    const float mu = mu_s, inv = inv_s;
    float4 wv = *reinterpret_cast<const float4*>(&w[tid * 4]);
    float4 bv = *reinterpret_cast<const float4*>(&bia[tid * 4]);
    float4 o;
    o.x = (v.x - mu) * inv * wv.x + bv.x;
    o.y = (v.y - mu) * inv * wv.y + bv.y;
    o.z = (v.z - mu) * inv * wv.z + bv.z;
    o.w = (v.w - mu) * inv * wv.w + bv.w;
    *reinterpret_cast<float4*>(&out[(size_t)row * C_DIM + tid * 4]) = o;
}

// =====================================================================
// launch
// =====================================================================
extern "C" void kernel_launch(void* const* d_in, const int* in_sizes, int n_in,
                              void* d_out, int out_size)
{
    (void)in_sizes; (void)n_in; (void)out_size;
    const float* x    = (const float*)d_in[0];
    const float* W1q  = (const float*)d_in[1];
    const float* b1q  = (const float*)d_in[2];
    const float* W2q  = (const float*)d_in[3];
    const float* b2q  = (const float*)d_in[4];
    const float* W1k  = (const float*)d_in[5];
    const float* b1k  = (const float*)d_in[6];
    const float* W2k  = (const float*)d_in[7];
    const float* b2k  = (const float*)d_in[8];
    const float* W1v  = (const float*)d_in[9];
    const float* b1v  = (const float*)d_in[10];
    const float* W2v  = (const float*)d_in[11];
    const float* b2v  = (const float*)d_in[12];
    const float* ln_w = (const float*)d_in[13];
    const float* ln_b = (const float*)d_in[14];
    float* out = (float*)d_out;

    __nv_bfloat16 *xh, *xl, *hh, *hl, *qh, *ql, *sh, *sl, *vth, *vtl, *wh, *wl;
    float* o;
    cudaGetSymbolAddress((void**)&xh,  g_xh);  cudaGetSymbolAddress((void**)&xl,  g_xl);
    cudaGetSymbolAddress((void**)&hh,  g_hh);  cudaGetSymbolAddress((void**)&hl,  g_hl);
    cudaGetSymbolAddress((void**)&qh,  g_qh);  cudaGetSymbolAddress((void**)&ql,  g_ql);
    cudaGetSymbolAddress((void**)&sh,  g_sh);  cudaGetSymbolAddress((void**)&sl,  g_sl);
    cudaGetSymbolAddress((void**)&vth, g_vth); cudaGetSymbolAddress((void**)&vtl, g_vtl);
    cudaGetSymbolAddress((void**)&wh,  g_wh);  cudaGetSymbolAddress((void**)&wl,  g_wl);
    cudaGetSymbolAddress((void**)&o,   g_o);

    cudaFuncSetAttribute(mma_gemm<0, false, false, false, true >, cudaFuncAttributeMaxDynamicSharedMemorySize, SMEMB);
    cudaFuncSetAttribute(mma_gemm<1, false, false, false, true >, cudaFuncAttributeMaxDynamicSharedMemorySize, SMEMB);
    cudaFuncSetAttribute(mma_gemm<2, true,  false, false, true >, cudaFuncAttributeMaxDynamicSharedMemorySize, SMEMB);
    cudaFuncSetAttribute(mma_gemm<3, false, true,  true,  false>, cudaFuncAttributeMaxDynamicSharedMemorySize, SMEMB);

    const float inv_scale = 1.0f / sqrtf((float)C_DIM * (float)T_SEQ);
    const long long CC = (long long)C_DIM * C_DIM;
    const long long MC = (long long)M_TOTAL * C_DIM;
    const long long TC = (long long)T_SEQ * C_DIM;
    const long long TT = (long long)T_SEQ * T_SEQ;

    // ---- prep: split x, transpose+split all weights (one launch) ----
    split_x_kernel<<<M_TOTAL * C_DIM / (256 * 4), 256>>>(
        (const float4*)x, (uint2*)xh, (uint2*)xl);
    dim3 tb(32, 8);
    WPack wp; wp.w[0] = W1q; wp.w[1] = W1k; wp.w[2] = W1v;
              wp.w[3] = W2q; wp.w[4] = W2k; wp.w[5] = W2v;
    wsplit_kernel<<<dim3(32, 32, 6), tb>>>(wp, wh, wl);

    // ---- MLP layer 1: h_z = GELU(x @ W1_z + b1_z), split output ----
    mma_gemm<0, false, false, false, true><<<dim3(C_DIM / BN, M_TOTAL / BM, 3), 256, SMEMB>>>(
        xh, xl, wh, wl, b1q, b1k, b1v, nullptr, hh, hl,
        C_DIM, C_DIM, C_DIM, C_DIM, 0, CC, MC, 0.0f);
    // ---- MLP layer 2: qkv_z = h_z @ W2_z + b2_z, split output ----
    mma_gemm<1, false, false, false, true><<<dim3(C_DIM / BN, M_TOTAL / BM, 3), 256, SMEMB>>>(
        hh, hl, wh + 3 * CC, wl + 3 * CC, b2q, b2k, b2v, nullptr, qh, ql,
        C_DIM, C_DIM, C_DIM, C_DIM, MC, CC, MC, 0.0f);

    // ---- V^T per batch (both planes) ----
    vtrans_kernel<<<dim3(C_DIM / 32, T_SEQ / 32, BATCH), tb>>>(
        qh + 2 * MC, ql + 2 * MC, vth, vtl);

    // ---- scores: S = mask(i>=j) * (q.k) * inv_scale, split output ----
    mma_gemm<2, true, false, false, true><<<dim3(T_SEQ / BN, T_SEQ / BM, BATCH), 256, SMEMB>>>(
        qh, ql, qh + MC, ql + MC, nullptr, nullptr, nullptr, nullptr, sh, sl,
        C_DIM, C_DIM, T_SEQ, C_DIM, TC, TC, TT, inv_scale);

    // ---- att: O = S @ V (causal K-limit, longest CTAs first), fp32 out ----
    mma_gemm<3, false, true, true, false><<<dim3(C_DIM / BN, T_SEQ / BM, BATCH), 256, SMEMB>>>(
        sh, sl, vth, vtl, nullptr, nullptr, nullptr, o, nullptr, nullptr,
        T_SEQ, T_SEQ, C_DIM, T_SEQ, TT, (long long)C_DIM * T_SEQ, TC, 0.0f);

    layernorm_kernel<<<M_TOTAL, 256>>>(o, ln_w, ln_b, out);
}

// round 15
// speedup vs baseline: 1.0086x; 1.0000x over previous
#include <cuda_runtime.h>
#include <cuda_bf16.h>
#include <math.h>
#include <stdint.h>

// ---------------- problem constants ----------------
#define C_DIM   1024
#define T_SEQ   2048
#define BATCH   8
#define M_TOTAL (BATCH * T_SEQ)       // 16384

// ---------------- tile config ----------------
#define BM 128
#define BN 128
#define BKF 32                         // k-values per chunk
#define ROWB 64                        // 32 bf16 per row, XOR-swizzled chunks
#define TILEB (128 * ROWB)             // 8192 B per plane tile
#define STAGEB (4 * TILEB)             // Ah,Al,Bh,Bl = 32768 B per stage
#define NSTAGE 3
#define SMEMB  (NSTAGE * STAGEB)       // 98304 B

// ---------------- scratch: split bf16 planes ----------------
__device__ __nv_bfloat16 g_xh [(size_t)M_TOTAL * C_DIM];
__device__ __nv_bfloat16 g_xl [(size_t)M_TOTAL * C_DIM];
__device__ __nv_bfloat16 g_hh [(size_t)3 * M_TOTAL * C_DIM];
__device__ __nv_bfloat16 g_hl [(size_t)3 * M_TOTAL * C_DIM];
__device__ __nv_bfloat16 g_qh [(size_t)3 * M_TOTAL * C_DIM];   // q|k|v planes
__device__ __nv_bfloat16 g_ql [(size_t)3 * M_TOTAL * C_DIM];
__device__ __nv_bfloat16 g_sh [(size_t)BATCH * T_SEQ * T_SEQ];
__device__ __nv_bfloat16 g_sl [(size_t)BATCH * T_SEQ * T_SEQ];
__device__ __nv_bfloat16 g_vth[(size_t)BATCH * C_DIM * T_SEQ];
__device__ __nv_bfloat16 g_vtl[(size_t)BATCH * C_DIM * T_SEQ];
__device__ __nv_bfloat16 g_wh [(size_t)6 * C_DIM * C_DIM];
__device__ __nv_bfloat16 g_wl [(size_t)6 * C_DIM * C_DIM];
__device__ float         g_o  [(size_t)M_TOTAL * C_DIM];

// weight pointer pack for the fused wsplit launch
struct WPack { const float* w[6]; };

// ---------------- helpers ----------------
__device__ __forceinline__ uint32_t smem_u32(const void* p) {
    uint32_t a;
    asm("{ .reg .u64 t; cvta.to.shared.u64 t, %1; cvt.u32.u64 %0, t; }" : "=r"(a) : "l"(p));
    return a;
}
__device__ __forceinline__ void ldsm4(uint32_t* r, uint32_t addr) {
    asm volatile("ldmatrix.sync.aligned.m8n8.x4.shared.b16 {%0,%1,%2,%3}, [%4];"
                 : "=r"(r[0]), "=r"(r[1]), "=r"(r[2]), "=r"(r[3]) : "r"(addr));
}
__device__ __forceinline__ void mma16816(float* c, const uint32_t* a, uint32_t b0, uint32_t b1) {
    asm volatile("mma.sync.aligned.m16n8k16.row.col.f32.bf16.bf16.f32 "
                 "{%0,%1,%2,%3}, {%4,%5,%6,%7}, {%8,%9}, {%0,%1,%2,%3};"
                 : "+f"(c[0]), "+f"(c[1]), "+f"(c[2]), "+f"(c[3])
                 : "r"(a[0]), "r"(a[1]), "r"(a[2]), "r"(a[3]), "r"(b0), "r"(b1));
}
__device__ __forceinline__ void cpa16(uint32_t dst, const void* src) {
    asm volatile("cp.async.cg.shared.global [%0], [%1], 16;" :: "r"(dst), "l"(src));
}
__device__ __forceinline__ void cpa_commit() { asm volatile("cp.async.commit_group;" ::: "memory"); }
template <int N> __device__ __forceinline__ void cpa_wait() {
    asm volatile("cp.async.wait_group %0;" :: "n"(N) : "memory");
}
__device__ __forceinline__ float gelu_exact(float x) {
    return 0.5f * x * (1.0f + erff(x * 0.70710678118654752440f));
}
// (a,b) fp32 -> packed bf16x2 hi + lo
__device__ __forceinline__ void split2(float a, float b, uint32_t& hi, uint32_t& lo) {
    __nv_bfloat162 h = __floats2bfloat162_rn(a, b);
    __nv_bfloat162 l = __floats2bfloat162_rn(a - __bfloat162float(h.x),
                                             b - __bfloat162float(h.y));
    hi = *reinterpret_cast<uint32_t*>(&h);
    lo = *reinterpret_cast<uint32_t*>(&l);
}

// =====================================================================
// bf16x3 tensor-core GEMM on pre-split planes, 3-stage cp.async ring,
// with parity-staggered k-loop start.
//   C[m,n] = epi( sum_k A[m,k]*B[n,k] ),  A=Ah+Al, B=Bh+Bl
//   EPI: 0 bias+GELU, 1 bias, 2 causal mask*scale, 3 plain
//   SKIP: skip CTA if bn > bm+127; CK: K limit = bm+128
//   REVY: reverse blockIdx.y (longest causal CTAs launch first)
//   OSPLIT: write split bf16 hi/lo planes instead of fp32
// =====================================================================
template <int EPI, bool SKIP, bool CK, bool REVY, bool OSPLIT>
__global__ __launch_bounds__(256, 2)
void mma_gemm(const __nv_bfloat16* __restrict__ Ah, const __nv_bfloat16* __restrict__ Al,
              const __nv_bfloat16* __restrict__ Bh, const __nv_bfloat16* __restrict__ Bl,
              const float* __restrict__ b0, const float* __restrict__ b1,
              const float* __restrict__ b2,
              float* __restrict__ Co, __nv_bfloat16* __restrict__ Ch,
              __nv_bfloat16* __restrict__ Cl,
              int lda, int ldb, int ldc, int kdim,
              long long sA, long long sB, long long sC, float scale)
{
    const int by = REVY ? (gridDim.y - 1 - blockIdx.y) : blockIdx.y;
    const int bm = by * BM;
    const int bn = blockIdx.x * BN;
    if (SKIP && bn > bm + (BM - 1)) return;
    const int z = blockIdx.z;
    Ah += (size_t)z * sA; Al += (size_t)z * sA;
    Bh += (size_t)z * sB; Bl += (size_t)z * sB;
    if (OSPLIT) { Ch += (size_t)z * sC; Cl += (size_t)z * sC; }
    else        { Co += (size_t)z * sC; }
    const float* bias = (z == 0) ? b0 : ((z == 1) ? b1 : b2);

    extern __shared__ __align__(128) char smem[];
    const uint32_t sb = smem_u32(smem);
    const int tid = threadIdx.x, lane = tid & 31, wid = tid >> 5;
    const int wm = (wid >> 1) * 32;
    const int wn = (wid & 1) * 64;

    const int kend = CK ? (bm + BM) : kdim;
    const int NC = kend / BKF;

    // parity of linear bid approximates co-residency pairing; odd CTAs
    // start half a k-loop ahead -> barriers interleave across the pair
    const int par = (int)((blockIdx.x + gridDim.x * (blockIdx.y + gridDim.y * blockIdx.z)) & 1);
    const int c0 = par * (NC / 2);

    // cp.async mapping: r0 = row, chunk c = tid&3, XOR-swizzled by (row>>1)&3
    const int r0 = tid >> 2;
    const int ck = tid & 3;
    const uint32_t sw0 = (uint32_t)((r0 >> 1) & 3);             // same for r0 and r0+64
    const uint32_t so0 = (uint32_t)r0 * ROWB + ((ck ^ sw0) * 16);
    const uint32_t so1 = so0 + 64u * ROWB;
    const int kc = ck * 8;                                       // bf16 elem offset

    auto issue = [&](int t) {
        int p = c0 + t; if (p >= NC) p -= NC;                    // staggered chunk id
        const int k0 = p * BKF;
        const uint32_t stg = sb + (uint32_t)(t % NSTAGE) * STAGEB;
        cpa16(stg + 0 * TILEB + so0, Ah + (size_t)(bm + r0) * lda + k0 + kc);
        cpa16(stg + 1 * TILEB + so0, Al + (size_t)(bm + r0) * lda + k0 + kc);
        cpa16(stg + 2 * TILEB + so0, Bh + (size_t)(bn + r0) * ldb + k0 + kc);
        cpa16(stg + 3 * TILEB + so0, Bl + (size_t)(bn + r0) * ldb + k0 + kc);
        cpa16(stg + 0 * TILEB + so1, Ah + (size_t)(bm + r0 + 64) * lda + k0 + kc);
        cpa16(stg + 1 * TILEB + so1, Al + (size_t)(bm + r0 + 64) * lda + k0 + kc);
        cpa16(stg + 2 * TILEB + so1, Bh + (size_t)(bn + r0 + 64) * ldb + k0 + kc);
        cpa16(stg + 3 * TILEB + so1, Bl + (size_t)(bn + r0 + 64) * ldb + k0 + kc);
        cpa_commit();
    };

    float acc[2][8][4];
    #pragma unroll
    for (int mt = 0; mt < 2; mt++)
        #pragma unroll
        for (int nt = 0; nt < 8; nt++)
            #pragma unroll
            for (int e = 0; e < 4; e++) acc[mt][nt][e] = 0.0f;

    const uint32_t lrow = lane & 15;
    const uint32_t lc16 = (uint32_t)(lane >> 4);   // chunk sub-index from lane

    // precompute per-thread ldmatrix row offsets (swizzle depends on row)
    uint32_t aoff[2], boff[4];
    #pragma unroll
    for (int mt = 0; mt < 2; mt++) {
        const uint32_t row = (uint32_t)(wm + mt * 16) + lrow;
        aoff[mt] = row * ROWB + (((row >> 1) & 3) << 4);
    }
    #pragma unroll
    for (int ng = 0; ng < 4; ng++) {
        const uint32_t row = (uint32_t)(wn + ng * 16) + lrow;
        boff[ng] = row * ROWB + (((row >> 1) & 3) << 4);
    }

    issue(0);
    if (NC > 1) issue(1);

    for (int t = 0; t < NC; t++) {
        if (t + 1 < NC) cpa_wait<1>(); else cpa_wait<0>();
        __syncthreads();
        if (t + 2 < NC) issue(t + 2);    // safe: targets buffer consumed at t-1
        const uint32_t stg = sb + (uint32_t)(t % NSTAGE) * STAGEB;

        #pragma unroll
        for (int s = 0; s < 2; s++) {
            const uint32_t chunk = ((uint32_t)s * 2 + lc16) << 4;
            uint32_t ah[2][4], al[2][4];
            #pragma unroll
            for (int mt = 0; mt < 2; mt++) {
                const uint32_t ad = stg + (aoff[mt] ^ chunk);
                ldsm4(ah[mt], ad);
                ldsm4(al[mt], ad + 1 * TILEB);
            }
            #pragma unroll
            for (int ng = 0; ng < 4; ng++) {
                uint32_t bh[4], bl[4];
                const uint32_t bd = stg + (boff[ng] ^ chunk);
                ldsm4(bh, bd + 2 * TILEB);
                ldsm4(bl, bd + 3 * TILEB);
                // term 1: Ahi * Bhi  (4 independent accumulators)
                mma16816(acc[0][2 * ng],     ah[0], bh[0], bh[2]);
                mma16816(acc[0][2 * ng + 1], ah[0], bh[1], bh[3]);
                mma16816(acc[1][2 * ng],     ah[1], bh[0], bh[2]);
                mma16816(acc[1][2 * ng + 1], ah[1], bh[1], bh[3]);
                // term 2: Ahi * Blo
                mma16816(acc[0][2 * ng],     ah[0], bl[0], bl[2]);
                mma16816(acc[0][2 * ng + 1], ah[0], bl[1], bl[3]);
                mma16816(acc[1][2 * ng],     ah[1], bl[0], bl[2]);
                mma16816(acc[1][2 * ng + 1], ah[1], bl[1], bl[3]);
                // term 3: Alo * Bhi
                mma16816(acc[0][2 * ng],     al[0], bh[0], bh[2]);
                mma16816(acc[0][2 * ng + 1], al[0], bh[1], bh[3]);
                mma16816(acc[1][2 * ng],     al[1], bh[0], bh[2]);
                mma16816(acc[1][2 * ng + 1], al[1], bh[1], bh[3]);
            }
        }
    }

    // ---- epilogue ----
    const int erow = lane >> 2;
    const int ecol = (lane & 3) * 2;
    #pragma unroll
    for (int mt = 0; mt < 2; mt++) {
        #pragma unroll
        for (int nt = 0; nt < 8; nt++) {
            const int gr = bm + wm + mt * 16 + erow;
            const int gc = bn + wn + nt * 8 + ecol;
            float v0 = acc[mt][nt][0], v1 = acc[mt][nt][1];
            float v2 = acc[mt][nt][2], v3 = acc[mt][nt][3];
            if (EPI == 0) {
                const float bb0 = bias[gc], bb1 = bias[gc + 1];
                v0 = gelu_exact(v0 + bb0); v1 = gelu_exact(v1 + bb1);
                v2 = gelu_exact(v2 + bb0); v3 = gelu_exact(v3 + bb1);
            } else if (EPI == 1) {
                const float bb0 = bias[gc], bb1 = bias[gc + 1];
                v0 += bb0; v1 += bb1; v2 += bb0; v3 += bb1;
            } else if (EPI == 2) {
                v0 = (gr     >= gc    ) ? v0 * scale : 0.0f;
                v1 = (gr     >= gc + 1) ? v1 * scale : 0.0f;
                v2 = (gr + 8 >= gc    ) ? v2 * scale : 0.0f;
                v3 = (gr + 8 >= gc + 1) ? v3 * scale : 0.0f;
            }
            if (OSPLIT) {
                uint32_t h01, l01, h23, l23;
                split2(v0, v1, h01, l01);
                split2(v2, v3, h23, l23);
                *reinterpret_cast<uint32_t*>(Ch + (size_t)gr * ldc + gc)       = h01;
                *reinterpret_cast<uint32_t*>(Cl + (size_t)gr * ldc + gc)       = l01;
                *reinterpret_cast<uint32_t*>(Ch + (size_t)(gr + 8) * ldc + gc) = h23;
                *reinterpret_cast<uint32_t*>(Cl + (size_t)(gr + 8) * ldc + gc) = l23;
            } else {
                *reinterpret_cast<float2*>(Co + (size_t)gr * ldc + gc)       = make_float2(v0, v1);
                *reinterpret_cast<float2*>(Co + (size_t)(gr + 8) * ldc + gc) = make_float2(v2, v3);
            }
        }
    }
}

// =====================================================================
// x split: fp32 -> bf16 hi/lo planes
// =====================================================================
__global__ __launch_bounds__(256) void split_x_kernel(
    const float4* __restrict__ x, uint2* __restrict__ hi, uint2* __restrict__ lo)
{
    const int i = blockIdx.x * 256 + threadIdx.x;
    float4 v = x[i];
    uint32_t h01, l01, h23, l23;
    split2(v.x, v.y, h01, l01);
    split2(v.z, v.w, h23, l23);
    hi[i] = make_uint2(h01, h23);
    lo[i] = make_uint2(l01, l23);
}

// =====================================================================
// fused weight transpose+split: all 6 W[k,n] fp32 -> wh/wl [n,k] bf16
// =====================================================================
__global__ __launch_bounds__(256) void wsplit_kernel(
    WPack wp, __nv_bfloat16* __restrict__ wh, __nv_bfloat16* __restrict__ wl)
{
    __shared__ float t[32][33];
    const int z = blockIdx.z;
    const float* W = wp.w[z];
    __nv_bfloat16* whz = wh + (size_t)z * C_DIM * C_DIM;
    __nv_bfloat16* wlz = wl + (size_t)z * C_DIM * C_DIM;
    const int n0 = blockIdx.x * 32, k0 = blockIdx.y * 32;
    const int tx = threadIdx.x, ty = threadIdx.y;
    #pragma unroll
    for (int i = ty; i < 32; i += 8)
        t[i][tx] = W[(size_t)(k0 + i) * C_DIM + n0 + tx];
    __syncthreads();
    #pragma unroll
    for (int i = ty; i < 32; i += 8) {
        float v = t[tx][i];
        __nv_bfloat16 h = __float2bfloat16(v);
        whz[(size_t)(n0 + i) * C_DIM + k0 + tx] = h;
        wlz[(size_t)(n0 + i) * C_DIM + k0 + tx] = __float2bfloat16(v - __bfloat162float(h));
    }
}

// =====================================================================
// V transpose (both planes): [T,C] -> [C,T], batched over z
// =====================================================================
__global__ __launch_bounds__(256) void vtrans_kernel(
    const __nv_bfloat16* __restrict__ vh, const __nv_bfloat16* __restrict__ vl,
    __nv_bfloat16* __restrict__ vth, __nv_bfloat16* __restrict__ vtl)
{
    __shared__ ushort th[32][33], tl[32][33];
    const int z = blockIdx.z;
    const ushort* ph = reinterpret_cast<const ushort*>(vh) + (size_t)z * T_SEQ * C_DIM;
    const ushort* pl = reinterpret_cast<const ushort*>(vl) + (size_t)z * T_SEQ * C_DIM;
    ushort* oh = reinterpret_cast<ushort*>(vth) + (size_t)z * C_DIM * T_SEQ;
    ushort* ol = reinterpret_cast<ushort*>(vtl) + (size_t)z * C_DIM * T_SEQ;
    const int c0 = blockIdx.x * 32, r0 = blockIdx.y * 32;
    const int tx = threadIdx.x, ty = threadIdx.y;
    #pragma unroll
    for (int i = ty; i < 32; i += 8) {
        th[i][tx] = ph[(size_t)(r0 + i) * C_DIM + c0 + tx];
        tl[i][tx] = pl[(size_t)(r0 + i) * C_DIM + c0 + tx];
    }
    __syncthreads();
    #pragma unroll
    for (int i = ty; i < 32; i += 8) {
        oh[(size_t)(c0 + i) * T_SEQ + r0 + tx] = th[tx][i];
        ol[(size_t)(c0 + i) * T_SEQ + r0 + tx] = tl[tx][i];
    }
}

// =====================================================================
// LayerNorm over last dim (C=1024), weight+bias, eps=1e-5
// =====================================================================
__global__ __launch_bounds__(256) void layernorm_kernel(
    const float* __restrict__ X, const float* __restrict__ w,
    const float* __restrict__ bia, float* __restrict__ out)
{
    const int row = blockIdx.x;
    const int tid = threadIdx.x;
    const float* xr = X + (size_t)row * C_DIM;

    float4 v = *reinterpret_cast<const float4*>(&xr[tid * 4]);
    float s  = v.x + v.y + v.z + v.w;
    float sq = v.x * v.x + v.y * v.y + v.z * v.z + v.w * v.w;
    #pragma unroll
    for (int off = 16; off > 0; off >>= 1) {
        s  += __shfl_xor_sync(0xffffffffu, s,  off);
        sq += __shfl_xor_sync(0xffffffffu, sq, off);
    }
    __shared__ float red_s[8], red_q[8];
    const int wid = tid >> 5;
    if ((tid & 31) == 0) { red_s[wid] = s; red_q[wid] = sq; }
    __syncthreads();
    __shared__ float mu_s, inv_s;
    if (tid == 0) {
        float ts = 0.f, tq = 0.f;
        #pragma unroll
        for (int i = 0; i < 8; i++) { ts += red_s[i]; tq += red_q[i]; }
        float mu  = ts * (1.0f / C_DIM);
        float var = tq * (1.0f / C_DIM) - mu * mu;
        mu_s = mu; inv_s = rsqrtf(var + 1e-5f);
    }
    __syncthreads();
    const float mu = mu_s, inv = inv_s;
    float4 wv = *reinterpret_cast<const float4*>(&w[tid * 4]);
    float4 bv = *reinterpret_cast<const float4*>(&bia[tid * 4]);
    float4 o;
    o.x = (v.x - mu) * inv * wv.x + bv.x;
    o.y = (v.y - mu) * inv * wv.y + bv.y;
    o.z = (v.z - mu) * inv * wv.z + bv.z;
    o.w = (v.w - mu) * inv * wv.w + bv.w;
    *reinterpret_cast<float4*>(&out[(size_t)row * C_DIM + tid * 4]) = o;
}

// =====================================================================
// launch
// =====================================================================
extern "C" void kernel_launch(void* const* d_in, const int* in_sizes, int n_in,
                              void* d_out, int out_size)
{
    (void)in_sizes; (void)n_in; (void)out_size;
    const float* x    = (const float*)d_in[0];
    const float* W1q  = (const float*)d_in[1];
    const float* b1q  = (const float*)d_in[2];
    const float* W2q  = (const float*)d_in[3];
    const float* b2q  = (const float*)d_in[4];
    const float* W1k  = (const float*)d_in[5];
    const float* b1k  = (const float*)d_in[6];
    const float* W2k  = (const float*)d_in[7];
    const float* b2k  = (const float*)d_in[8];
    const float* W1v  = (const float*)d_in[9];
    const float* b1v  = (const float*)d_in[10];
    const float* W2v  = (const float*)d_in[11];
    const float* b2v  = (const float*)d_in[12];
    const float* ln_w = (const float*)d_in[13];
    const float* ln_b = (const float*)d_in[14];
    float* out = (float*)d_out;

    __nv_bfloat16 *xh, *xl, *hh, *hl, *qh, *ql, *sh, *sl, *vth, *vtl, *wh, *wl;
    float* o;
    cudaGetSymbolAddress((void**)&xh,  g_xh);  cudaGetSymbolAddress((void**)&xl,  g_xl);
    cudaGetSymbolAddress((void**)&hh,  g_hh);  cudaGetSymbolAddress((void**)&hl,  g_hl);
    cudaGetSymbolAddress((void**)&qh,  g_qh);  cudaGetSymbolAddress((void**)&ql,  g_ql);
    cudaGetSymbolAddress((void**)&sh,  g_sh);  cudaGetSymbolAddress((void**)&sl,  g_sl);
    cudaGetSymbolAddress((void**)&vth, g_vth); cudaGetSymbolAddress((void**)&vtl, g_vtl);
    cudaGetSymbolAddress((void**)&wh,  g_wh);  cudaGetSymbolAddress((void**)&wl,  g_wl);
    cudaGetSymbolAddress((void**)&o,   g_o);

    cudaFuncSetAttribute(mma_gemm<0, false, false, false, true >, cudaFuncAttributeMaxDynamicSharedMemorySize, SMEMB);
    cudaFuncSetAttribute(mma_gemm<1, false, false, false, true >, cudaFuncAttributeMaxDynamicSharedMemorySize, SMEMB);
    cudaFuncSetAttribute(mma_gemm<2, true,  false, false, true >, cudaFuncAttributeMaxDynamicSharedMemorySize, SMEMB);
    cudaFuncSetAttribute(mma_gemm<3, false, true,  true,  false>, cudaFuncAttributeMaxDynamicSharedMemorySize, SMEMB);

    const float inv_scale = 1.0f / sqrtf((float)C_DIM * (float)T_SEQ);
    const long long CC = (long long)C_DIM * C_DIM;
    const long long MC = (long long)M_TOTAL * C_DIM;
    const long long TC = (long long)T_SEQ * C_DIM;
    const long long TT = (long long)T_SEQ * T_SEQ;

    // ---- prep: split x, transpose+split all weights (one launch) ----
    split_x_kernel<<<M_TOTAL * C_DIM / (256 * 4), 256>>>(
        (const float4*)x, (uint2*)xh, (uint2*)xl);
    dim3 tb(32, 8);
    WPack wp; wp.w[0] = W1q; wp.w[1] = W1k; wp.w[2] = W1v;
              wp.w[3] = W2q; wp.w[4] = W2k; wp.w[5] = W2v;
    wsplit_kernel<<<dim3(32, 32, 6), tb>>>(wp, wh, wl);

    // ---- MLP layer 1: h_z = GELU(x @ W1_z + b1_z), split output ----
    mma_gemm<0, false, false, false, true><<<dim3(C_DIM / BN, M_TOTAL / BM, 3), 256, SMEMB>>>(
        xh, xl, wh, wl, b1q, b1k, b1v, nullptr, hh, hl,
        C_DIM, C_DIM, C_DIM, C_DIM, 0, CC, MC, 0.0f);
    // ---- MLP layer 2: qkv_z = h_z @ W2_z + b2_z, split output ----
    mma_gemm<1, false, false, false, true><<<dim3(C_DIM / BN, M_TOTAL / BM, 3), 256, SMEMB>>>(
        hh, hl, wh + 3 * CC, wl + 3 * CC, b2q, b2k, b2v, nullptr, qh, ql,
        C_DIM, C_DIM, C_DIM, C_DIM, MC, CC, MC, 0.0f);

    // ---- V^T per batch (both planes) ----
    vtrans_kernel<<<dim3(C_DIM / 32, T_SEQ / 32, BATCH), tb>>>(
        qh + 2 * MC, ql + 2 * MC, vth, vtl);

    // ---- scores: S = mask(i>=j) * (q.k) * inv_scale, split output ----
    mma_gemm<2, true, false, false, true><<<dim3(T_SEQ / BN, T_SEQ / BM, BATCH), 256, SMEMB>>>(
        qh, ql, qh + MC, ql + MC, nullptr, nullptr, nullptr, nullptr, sh, sl,
        C_DIM, C_DIM, T_SEQ, C_DIM, TC, TC, TT, inv_scale);

    // ---- att: O = S @ V (causal K-limit, longest CTAs first), fp32 out ----
    mma_gemm<3, false, true, true, false><<<dim3(C_DIM / BN, T_SEQ / BM, BATCH), 256, SMEMB>>>(
        sh, sl, vth, vtl, nullptr, nullptr, nullptr, o, nullptr, nullptr,
        T_SEQ, T_SEQ, C_DIM, T_SEQ, TT, (long long)C_DIM * T_SEQ, TC, 0.0f);

    layernorm_kernel<<<M_TOTAL, 256>>>(o, ln_w, ln_b, out);
}

// round 17
// speedup vs baseline: 1.0476x; 1.0387x over previous
#include <cuda_runtime.h>
#include <cuda_bf16.h>
#include <math.h>
#include <stdint.h>

// ---------------- problem constants ----------------
#define C_DIM   1024
#define T_SEQ   2048
#define BATCH   8
#define M_TOTAL (BATCH * T_SEQ)       // 16384

// ---------------- tile config ----------------
#define BM 128
#define BN 128
#define BKF 32                         // k-values per chunk
#define ROWB 64                        // 32 bf16 per row, XOR-swizzled chunks
#define TILEB (128 * ROWB)             // 8192 B per plane tile
#define STAGEB (4 * TILEB)             // Ah,Al,Bh,Bl = 32768 B per stage
#define NSTAGE 3
#define SMEMB  (NSTAGE * STAGEB)       // 98304 B

// ---------------- scratch: split bf16 planes ----------------
__device__ __nv_bfloat16 g_xh [(size_t)M_TOTAL * C_DIM];
__device__ __nv_bfloat16 g_xl [(size_t)M_TOTAL * C_DIM];
__device__ __nv_bfloat16 g_hh [(size_t)3 * M_TOTAL * C_DIM];
__device__ __nv_bfloat16 g_hl [(size_t)3 * M_TOTAL * C_DIM];
__device__ __nv_bfloat16 g_qh [(size_t)3 * M_TOTAL * C_DIM];   // q|k|v planes
__device__ __nv_bfloat16 g_ql [(size_t)3 * M_TOTAL * C_DIM];
__device__ __nv_bfloat16 g_sh [(size_t)BATCH * T_SEQ * T_SEQ];
__device__ __nv_bfloat16 g_sl [(size_t)BATCH * T_SEQ * T_SEQ];
__device__ __nv_bfloat16 g_wh [(size_t)6 * C_DIM * C_DIM];
__device__ __nv_bfloat16 g_wl [(size_t)6 * C_DIM * C_DIM];
__device__ float         g_o  [(size_t)M_TOTAL * C_DIM];

// weight pointer pack for the fused wsplit launch
struct WPack { const float* w[6]; };

// ---------------- helpers ----------------
__device__ __forceinline__ uint32_t smem_u32(const void* p) {
    uint32_t a;
    asm("{ .reg .u64 t; cvta.to.shared.u64 t, %1; cvt.u32.u64 %0, t; }" : "=r"(a) : "l"(p));
    return a;
}
__device__ __forceinline__ void ldsm4(uint32_t* r, uint32_t addr) {
    asm volatile("ldmatrix.sync.aligned.m8n8.x4.shared.b16 {%0,%1,%2,%3}, [%4];"
                 : "=r"(r[0]), "=r"(r[1]), "=r"(r[2]), "=r"(r[3]) : "r"(addr));
}
__device__ __forceinline__ void ldsm4t(uint32_t* r, uint32_t addr) {
    asm volatile("ldmatrix.sync.aligned.m8n8.x4.trans.shared.b16 {%0,%1,%2,%3}, [%4];"
                 : "=r"(r[0]), "=r"(r[1]), "=r"(r[2]), "=r"(r[3]) : "r"(addr));
}
__device__ __forceinline__ void mma16816(float* c, const uint32_t* a, uint32_t b0, uint32_t b1) {
    asm volatile("mma.sync.aligned.m16n8k16.row.col.f32.bf16.bf16.f32 "
                 "{%0,%1,%2,%3}, {%4,%5,%6,%7}, {%8,%9}, {%0,%1,%2,%3};"
                 : "+f"(c[0]), "+f"(c[1]), "+f"(c[2]), "+f"(c[3])
                 : "r"(a[0]), "r"(a[1]), "r"(a[2]), "r"(a[3]), "r"(b0), "r"(b1));
}
__device__ __forceinline__ void cpa16(uint32_t dst, const void* src) {
    asm volatile("cp.async.cg.shared.global [%0], [%1], 16;" :: "r"(dst), "l"(src));
}
__device__ __forceinline__ void cpa_commit() { asm volatile("cp.async.commit_group;" ::: "memory"); }
template <int N> __device__ __forceinline__ void cpa_wait() {
    asm volatile("cp.async.wait_group %0;" :: "n"(N) : "memory");
}
__device__ __forceinline__ float gelu_exact(float x) {
    return 0.5f * x * (1.0f + erff(x * 0.70710678118654752440f));
}
// (a,b) fp32 -> packed bf16x2 hi + lo
__device__ __forceinline__ void split2(float a, float b, uint32_t& hi, uint32_t& lo) {
    __nv_bfloat162 h = __floats2bfloat162_rn(a, b);
    __nv_bfloat162 l = __floats2bfloat162_rn(a - __bfloat162float(h.x),
                                             b - __bfloat162float(h.y));
    hi = *reinterpret_cast<uint32_t*>(&h);
    lo = *reinterpret_cast<uint32_t*>(&l);
}

// =====================================================================
// bf16x3 tensor-core GEMM on pre-split planes, 3-stage cp.async ring,
// with parity-staggered k-loop start.
//   TRB=false: B stored [n][k] (k-contiguous), non-trans ldmatrix.
//   TRB=true : B stored [k][n] (n-contiguous, e.g. natural V layout),
//              trans ldmatrix; B smem tile = 32 k-rows x 256 B with
//              chunk^(k&7) swizzle; b-pairs {r0,r1}/{r2,r3}.
//   C[m,n] = epi( sum_k A[m,k]*B~[k,n] )
//   EPI: 0 bias+GELU, 1 bias, 2 causal mask*scale, 3 plain
//   SKIP: skip CTA if bn > bm+127; CK: K limit = bm+128
//   REVY: reverse blockIdx.y (longest causal CTAs launch first)
//   OSPLIT: write split bf16 hi/lo planes instead of fp32
// =====================================================================
template <int EPI, bool SKIP, bool CK, bool REVY, bool OSPLIT, bool TRB>
__global__ __launch_bounds__(256, 2)
void mma_gemm(const __nv_bfloat16* __restrict__ Ah, const __nv_bfloat16* __restrict__ Al,
              const __nv_bfloat16* __restrict__ Bh, const __nv_bfloat16* __restrict__ Bl,
              const float* __restrict__ b0, const float* __restrict__ b1,
              const float* __restrict__ b2,
              float* __restrict__ Co, __nv_bfloat16* __restrict__ Ch,
              __nv_bfloat16* __restrict__ Cl,
              int lda, int ldb, int ldc, int kdim,
              long long sA, long long sB, long long sC, float scale)
{
    const int by = REVY ? (gridDim.y - 1 - blockIdx.y) : blockIdx.y;
    const int bm = by * BM;
    const int bn = blockIdx.x * BN;
    if (SKIP && bn > bm + (BM - 1)) return;
    const int z = blockIdx.z;
    Ah += (size_t)z * sA; Al += (size_t)z * sA;
    Bh += (size_t)z * sB; Bl += (size_t)z * sB;
    if (OSPLIT) { Ch += (size_t)z * sC; Cl += (size_t)z * sC; }
    else        { Co += (size_t)z * sC; }
    const float* bias = (z == 0) ? b0 : ((z == 1) ? b1 : b2);

    extern __shared__ __align__(128) char smem[];
    const uint32_t sb = smem_u32(smem);
    const int tid = threadIdx.x, lane = tid & 31, wid = tid >> 5;
    const int wm = (wid >> 1) * 32;
    const int wn = (wid & 1) * 64;

    const int kend = CK ? (bm + BM) : kdim;
    const int NC = kend / BKF;

    // parity of linear bid approximates co-residency pairing; odd CTAs
    // start half a k-loop ahead -> barriers interleave across the pair
    const int par = (int)((blockIdx.x + gridDim.x * (blockIdx.y + gridDim.y * blockIdx.z)) & 1);
    const int c0 = par * (NC / 2);

    // A cp.async mapping: r0 = row, chunk = tid&3, XOR-swizzled by (row>>1)&3
    const int r0 = tid >> 2;
    const int ck = tid & 3;
    const uint32_t sw0 = (uint32_t)((r0 >> 1) & 3);
    const uint32_t so0 = (uint32_t)r0 * ROWB + ((ck ^ sw0) * 16);
    const uint32_t so1 = so0 + 64u * ROWB;
    const int kc = ck * 8;

    // TRB B cp.async mapping: rbk = k-row (0..31), nsg = n-seg (0..7), two segs
    const int rbk = tid >> 3;
    const int nsg = tid & 7;
    const uint32_t bsw = (uint32_t)(rbk & 7);
    const uint32_t tb0 = (uint32_t)rbk * 256u + (((uint32_t)nsg ^ bsw) * 16u);
    const uint32_t tb1 = tb0 + 128u;            // seg nsg+8 -> (nsg^bsw)+8 chunks = +128 B

    auto issue = [&](int t) {
        int p = c0 + t; if (p >= NC) p -= NC;                    // staggered chunk id
        const int k0 = p * BKF;
        const uint32_t stg = sb + (uint32_t)(t % NSTAGE) * STAGEB;
        cpa16(stg + 0 * TILEB + so0, Ah + (size_t)(bm + r0) * lda + k0 + kc);
        cpa16(stg + 1 * TILEB + so0, Al + (size_t)(bm + r0) * lda + k0 + kc);
        cpa16(stg + 0 * TILEB + so1, Ah + (size_t)(bm + r0 + 64) * lda + k0 + kc);
        cpa16(stg + 1 * TILEB + so1, Al + (size_t)(bm + r0 + 64) * lda + k0 + kc);
        if (TRB) {
            const __nv_bfloat16* vbh = Bh + (size_t)(k0 + rbk) * ldb + bn + nsg * 8;
            const __nv_bfloat16* vbl = Bl + (size_t)(k0 + rbk) * ldb + bn + nsg * 8;
            cpa16(stg + 2 * TILEB + tb0, vbh);
            cpa16(stg + 3 * TILEB + tb0, vbl);
            cpa16(stg + 2 * TILEB + tb1, vbh + 64);
            cpa16(stg + 3 * TILEB + tb1, vbl + 64);
        } else {
            cpa16(stg + 2 * TILEB + so0, Bh + (size_t)(bn + r0) * ldb + k0 + kc);
            cpa16(stg + 3 * TILEB + so0, Bl + (size_t)(bn + r0) * ldb + k0 + kc);
            cpa16(stg + 2 * TILEB + so1, Bh + (size_t)(bn + r0 + 64) * ldb + k0 + kc);
            cpa16(stg + 3 * TILEB + so1, Bl + (size_t)(bn + r0 + 64) * ldb + k0 + kc);
        }
        cpa_commit();
    };

    float acc[2][8][4];
    #pragma unroll
    for (int mt = 0; mt < 2; mt++)
        #pragma unroll
        for (int nt = 0; nt < 8; nt++)
            #pragma unroll
            for (int e = 0; e < 4; e++) acc[mt][nt][e] = 0.0f;

    const uint32_t lrow = lane & 15;
    const uint32_t lc16 = (uint32_t)(lane >> 4);   // chunk sub-index from lane

    // per-thread ldmatrix row offsets
    uint32_t aoff[2], boff[4];
    #pragma unroll
    for (int mt = 0; mt < 2; mt++) {
        const uint32_t row = (uint32_t)(wm + mt * 16) + lrow;
        aoff[mt] = row * ROWB + (((row >> 1) & 3) << 4);
    }
    #pragma unroll
    for (int ng = 0; ng < 4; ng++) {
        if (TRB) {
            // lanes 0-15: k-rows 0-15 at n-half 0; lanes 16-31: at n-half 1
            const uint32_t cng = (uint32_t)(wn + ng * 16 + (int)(lc16 * 8)) >> 3;  // 16B chunk
            boff[ng] = lrow * 256u + ((cng ^ (lrow & 7u)) << 4);
        } else {
            const uint32_t row = (uint32_t)(wn + ng * 16) + lrow;
            boff[ng] = row * ROWB + (((row >> 1) & 3) << 4);
        }
    }

    issue(0);
    if (NC > 1) issue(1);

    for (int t = 0; t < NC; t++) {
        if (t + 1 < NC) cpa_wait<1>(); else cpa_wait<0>();
        __syncthreads();
        if (t + 2 < NC) issue(t + 2);    // safe: targets buffer consumed at t-1
        const uint32_t stg = sb + (uint32_t)(t % NSTAGE) * STAGEB;

        #pragma unroll
        for (int s = 0; s < 2; s++) {
            const uint32_t chunk = ((uint32_t)s * 2 + lc16) << 4;
            uint32_t ah[2][4], al[2][4];
            #pragma unroll
            for (int mt = 0; mt < 2; mt++) {
                const uint32_t ad = stg + (aoff[mt] ^ chunk);
                ldsm4(ah[mt], ad);
                ldsm4(al[mt], ad + 1 * TILEB);
            }
            #pragma unroll
            for (int ng = 0; ng < 4; ng++) {
                uint32_t bh[4], bl[4];
                if (TRB) {
                    const uint32_t bd = stg + boff[ng] + (uint32_t)s * 4096u;  // k-half: +16 rows
                    ldsm4t(bh, bd + 2 * TILEB);
                    ldsm4t(bl, bd + 3 * TILEB);
                } else {
                    const uint32_t bd = stg + (boff[ng] ^ chunk);
                    ldsm4(bh, bd + 2 * TILEB);
                    ldsm4(bl, bd + 3 * TILEB);
                }
                const uint32_t b00 = bh[0];
                const uint32_t b01 = TRB ? bh[1] : bh[2];
                const uint32_t b10 = TRB ? bh[2] : bh[1];
                const uint32_t b11 = bh[3];
                const uint32_t c00 = bl[0];
                const uint32_t c01 = TRB ? bl[1] : bl[2];
                const uint32_t c10 = TRB ? bl[2] : bl[1];
                const uint32_t c11 = bl[3];
                // term 1: Ahi * Bhi  (4 independent accumulators)
                mma16816(acc[0][2 * ng],     ah[0], b00, b01);
                mma16816(acc[0][2 * ng + 1], ah[0], b10, b11);
                mma16816(acc[1][2 * ng],     ah[1], b00, b01);
                mma16816(acc[1][2 * ng + 1], ah[1], b10, b11);
                // term 2: Ahi * Blo
                mma16816(acc[0][2 * ng],     ah[0], c00, c01);
                mma16816(acc[0][2 * ng + 1], ah[0], c10, c11);
                mma16816(acc[1][2 * ng],     ah[1], c00, c01);
                mma16816(acc[1][2 * ng + 1], ah[1], c10, c11);
                // term 3: Alo * Bhi
                mma16816(acc[0][2 * ng],     al[0], b00, b01);
                mma16816(acc[0][2 * ng + 1], al[0], b10, b11);
                mma16816(acc[1][2 * ng],     al[1], b00, b01);
                mma16816(acc[1][2 * ng + 1], al[1], b10, b11);
            }
        }
    }

    // ---- epilogue ----
    const int erow = lane >> 2;
    const int ecol = (lane & 3) * 2;
    #pragma unroll
    for (int mt = 0; mt < 2; mt++) {
        #pragma unroll
        for (int nt = 0; nt < 8; nt++) {
            const int gr = bm + wm + mt * 16 + erow;
            const int gc = bn + wn + nt * 8 + ecol;
            float v0 = acc[mt][nt][0], v1 = acc[mt][nt][1];
            float v2 = acc[mt][nt][2], v3 = acc[mt][nt][3];
            if (EPI == 0) {
                const float bb0 = bias[gc], bb1 = bias[gc + 1];
                v0 = gelu_exact(v0 + bb0); v1 = gelu_exact(v1 + bb1);
                v2 = gelu_exact(v2 + bb0); v3 = gelu_exact(v3 + bb1);
            } else if (EPI == 1) {
                const float bb0 = bias[gc], bb1 = bias[gc + 1];
                v0 += bb0; v1 += bb1; v2 += bb0; v3 += bb1;
            } else if (EPI == 2) {
                v0 = (gr     >= gc    ) ? v0 * scale : 0.0f;
                v1 = (gr     >= gc + 1) ? v1 * scale : 0.0f;
                v2 = (gr + 8 >= gc    ) ? v2 * scale : 0.0f;
                v3 = (gr + 8 >= gc + 1) ? v3 * scale : 0.0f;
            }
            if (OSPLIT) {
                uint32_t h01, l01, h23, l23;
                split2(v0, v1, h01, l01);
                split2(v2, v3, h23, l23);
                *reinterpret_cast<uint32_t*>(Ch + (size_t)gr * ldc + gc)       = h01;
                *reinterpret_cast<uint32_t*>(Cl + (size_t)gr * ldc + gc)       = l01;
                *reinterpret_cast<uint32_t*>(Ch + (size_t)(gr + 8) * ldc + gc) = h23;
                *reinterpret_cast<uint32_t*>(Cl + (size_t)(gr + 8) * ldc + gc) = l23;
            } else {
                *reinterpret_cast<float2*>(Co + (size_t)gr * ldc + gc)       = make_float2(v0, v1);
                *reinterpret_cast<float2*>(Co + (size_t)(gr + 8) * ldc + gc) = make_float2(v2, v3);
            }
        }
    }
}

// =====================================================================
// x split: fp32 -> bf16 hi/lo planes
// =====================================================================
__global__ __launch_bounds__(256) void split_x_kernel(
    const float4* __restrict__ x, uint2* __restrict__ hi, uint2* __restrict__ lo)
{
    const int i = blockIdx.x * 256 + threadIdx.x;
    float4 v = x[i];
    uint32_t h01, l01, h23, l23;
    split2(v.x, v.y, h01, l01);
    split2(v.z, v.w, h23, l23);
    hi[i] = make_uint2(h01, h23);
    lo[i] = make_uint2(l01, l23);
}

// =====================================================================
// fused weight transpose+split: all 6 W[k,n] fp32 -> wh/wl [n,k] bf16
// =====================================================================
__global__ __launch_bounds__(256) void wsplit_kernel(
    WPack wp, __nv_bfloat16* __restrict__ wh, __nv_bfloat16* __restrict__ wl)
{
    __shared__ float t[32][33];
    const int z = blockIdx.z;
    const float* W = wp.w[z];
    __nv_bfloat16* whz = wh + (size_t)z * C_DIM * C_DIM;
    __nv_bfloat16* wlz = wl + (size_t)z * C_DIM * C_DIM;
    const int n0 = blockIdx.x * 32, k0 = blockIdx.y * 32;
    const int tx = threadIdx.x, ty = threadIdx.y;
    #pragma unroll
    for (int i = ty; i < 32; i += 8)
        t[i][tx] = W[(size_t)(k0 + i) * C_DIM + n0 + tx];
    __syncthreads();
    #pragma unroll
    for (int i = ty; i < 32; i += 8) {
        float v = t[tx][i];
        __nv_bfloat16 h = __float2bfloat16(v);
        whz[(size_t)(n0 + i) * C_DIM + k0 + tx] = h;
        wlz[(size_t)(n0 + i) * C_DIM + k0 + tx] = __float2bfloat16(v - __bfloat162float(h));
    }
}

// =====================================================================
// LayerNorm over last dim (C=1024), weight+bias, eps=1e-5
// =====================================================================
__global__ __launch_bounds__(256) void layernorm_kernel(
    const float* __restrict__ X, const float* __restrict__ w,
    const float* __restrict__ bia, float* __restrict__ out)
{
    const int row = blockIdx.x;
    const int tid = threadIdx.x;
    const float* xr = X + (size_t)row * C_DIM;

    float4 v = *reinterpret_cast<const float4*>(&xr[tid * 4]);
    float s  = v.x + v.y + v.z + v.w;
    float sq = v.x * v.x + v.y * v.y + v.z * v.z + v.w * v.w;
    #pragma unroll
    for (int off = 16; off > 0; off >>= 1) {
        s  += __shfl_xor_sync(0xffffffffu, s,  off);
        sq += __shfl_xor_sync(0xffffffffu, sq, off);
    }
    __shared__ float red_s[8], red_q[8];
    const int wid = tid >> 5;
    if ((tid & 31) == 0) { red_s[wid] = s; red_q[wid] = sq; }
    __syncthreads();
    __shared__ float mu_s, inv_s;
    if (tid == 0) {
        float ts = 0.f, tq = 0.f;
        #pragma unroll
        for (int i = 0; i < 8; i++) { ts += red_s[i]; tq += red_q[i]; }
        float mu  = ts * (1.0f / C_DIM);
        float var = tq * (1.0f / C_DIM) - mu * mu;
        mu_s = mu; inv_s = rsqrtf(var + 1e-5f);
    }
    __syncthreads();
    const float mu = mu_s, inv = inv_s;
    float4 wv = *reinterpret_cast<const float4*>(&w[tid * 4]);
    float4 bv = *reinterpret_cast<const float4*>(&bia[tid * 4]);
    float4 o;
    o.x = (v.x - mu) * inv * wv.x + bv.x;
    o.y = (v.y - mu) * inv * wv.y + bv.y;
    o.z = (v.z - mu) * inv * wv.z + bv.z;
    o.w = (v.w - mu) * inv * wv.w + bv.w;
    *reinterpret_cast<float4*>(&out[(size_t)row * C_DIM + tid * 4]) = o;
}

// =====================================================================
// launch
// =====================================================================
extern "C" void kernel_launch(void* const* d_in, const int* in_sizes, int n_in,
                              void* d_out, int out_size)
{
    (void)in_sizes; (void)n_in; (void)out_size;
    const float* x    = (const float*)d_in[0];
    const float* W1q  = (const float*)d_in[1];
    const float* b1q  = (const float*)d_in[2];
    const float* W2q  = (const float*)d_in[3];
    const float* b2q  = (const float*)d_in[4];
    const float* W1k  = (const float*)d_in[5];
    const float* b1k  = (const float*)d_in[6];
    const float* W2k  = (const float*)d_in[7];
    const float* b2k  = (const float*)d_in[8];
    const float* W1v  = (const float*)d_in[9];
    const float* b1v  = (const float*)d_in[10];
    const float* W2v  = (const float*)d_in[11];
    const float* b2v  = (const float*)d_in[12];
    const float* ln_w = (const float*)d_in[13];
    const float* ln_b = (const float*)d_in[14];
    float* out = (float*)d_out;

    __nv_bfloat16 *xh, *xl, *hh, *hl, *qh, *ql, *sh, *sl, *wh, *wl;
    float* o;
    cudaGetSymbolAddress((void**)&xh,  g_xh);  cudaGetSymbolAddress((void**)&xl,  g_xl);
    cudaGetSymbolAddress((void**)&hh,  g_hh);  cudaGetSymbolAddress((void**)&hl,  g_hl);
    cudaGetSymbolAddress((void**)&qh,  g_qh);  cudaGetSymbolAddress((void**)&ql,  g_ql);
    cudaGetSymbolAddress((void**)&sh,  g_sh);  cudaGetSymbolAddress((void**)&sl,  g_sl);
    cudaGetSymbolAddress((void**)&wh,  g_wh);  cudaGetSymbolAddress((void**)&wl,  g_wl);
    cudaGetSymbolAddress((void**)&o,   g_o);

    cudaFuncSetAttribute(mma_gemm<0, false, false, false, true,  false>, cudaFuncAttributeMaxDynamicSharedMemorySize, SMEMB);
    cudaFuncSetAttribute(mma_gemm<1, false, false, false, true,  false>, cudaFuncAttributeMaxDynamicSharedMemorySize, SMEMB);
    cudaFuncSetAttribute(mma_gemm<2, true,  false, false, true,  false>, cudaFuncAttributeMaxDynamicSharedMemorySize, SMEMB);
    cudaFuncSetAttribute(mma_gemm<3, false, true,  true,  false, true >, cudaFuncAttributeMaxDynamicSharedMemorySize, SMEMB);

    const float inv_scale = 1.0f / sqrtf((float)C_DIM * (float)T_SEQ);
    const long long CC = (long long)C_DIM * C_DIM;
    const long long MC = (long long)M_TOTAL * C_DIM;
    const long long TC = (long long)T_SEQ * C_DIM;
    const long long TT = (long long)T_SEQ * T_SEQ;

    // ---- prep: split x, transpose+split all weights (one launch) ----
    split_x_kernel<<<M_TOTAL * C_DIM / (256 * 4), 256>>>(
        (const float4*)x, (uint2*)xh, (uint2*)xl);
    dim3 tb(32, 8);
    WPack wp; wp.w[0] = W1q; wp.w[1] = W1k; wp.w[2] = W1v;
              wp.w[3] = W2q; wp.w[4] = W2k; wp.w[5] = W2v;
    wsplit_kernel<<<dim3(32, 32, 6), tb>>>(wp, wh, wl);

    // ---- MLP layer 1: h_z = GELU(x @ W1_z + b1_z), split output ----
    mma_gemm<0, false, false, false, true, false><<<dim3(C_DIM / BN, M_TOTAL / BM, 3), 256, SMEMB>>>(
        xh, xl, wh, wl, b1q, b1k, b1v, nullptr, hh, hl,
        C_DIM, C_DIM, C_DIM, C_DIM, 0, CC, MC, 0.0f);
    // ---- MLP layer 2: qkv_z = h_z @ W2_z + b2_z, split output ----
    mma_gemm<1, false, false, false, true, false><<<dim3(C_DIM / BN, M_TOTAL / BM, 3), 256, SMEMB>>>(
        hh, hl, wh + 3 * CC, wl + 3 * CC, b2q, b2k, b2v, nullptr, qh, ql,
        C_DIM, C_DIM, C_DIM, C_DIM, MC, CC, MC, 0.0f);

    // ---- scores: S = mask(i>=j) * (q.k) * inv_scale, split output ----
    mma_gemm<2, true, false, false, true, false><<<dim3(T_SEQ / BN, T_SEQ / BM, BATCH), 256, SMEMB>>>(
        qh, ql, qh + MC, ql + MC, nullptr, nullptr, nullptr, nullptr, sh, sl,
        C_DIM, C_DIM, T_SEQ, C_DIM, TC, TC, TT, inv_scale);

    // ---- att: O = S @ V (causal K-limit, longest CTAs first), V read
    //      directly in natural [T,C] layout via trans ldmatrix ----
    mma_gemm<3, false, true, true, false, true><<<dim3(C_DIM / BN, T_SEQ / BM, BATCH), 256, SMEMB>>>(
        sh, sl, qh + 2 * MC, ql + 2 * MC, nullptr, nullptr, nullptr, o, nullptr, nullptr,
        T_SEQ, C_DIM, C_DIM, T_SEQ, TT, TC, TC, 0.0f);

    layernorm_kernel<<<M_TOTAL, 256>>>(o, ln_w, ln_b, out);
}